// round 11
// baseline (speedup 1.0000x reference)
#include <cuda_runtime.h>

#define TB 256
typedef unsigned long long ull;

__device__ __forceinline__ float fsig(float x) {
    float e = __expf(-x);
    return __fdividef(1.0f, 1.0f + e);
}
__device__ __forceinline__ float ftanh(float x) {
    float e = __expf(2.0f * x);
    return 1.0f - __fdividef(2.0f, e + 1.0f);
}
__device__ __forceinline__ ull pack2(float lo, float hi) {
    ull r; asm("mov.b64 %0, {%1, %2};" : "=l"(r) : "f"(lo), "f"(hi)); return r;
}
__device__ __forceinline__ ull dup2(float v) {
    ull r; asm("mov.b64 %0, {%1, %1};" : "=l"(r) : "f"(v)); return r;
}
__device__ __forceinline__ void unpack2(ull v, float& lo, float& hi) {
    asm("mov.b64 {%0, %1}, %2;" : "=f"(lo), "=f"(hi) : "l"(v));
}
#define FMA2(acc, w, a) asm("fma.rn.f32x2 %0, %1, %2, %0;" : "+l"(acc) : "l"(w), "l"(a))

#define PAIRBAR(g)  asm volatile("bar.sync %0, 64;"  :: "r"((g) + 1) : "memory")
#define GROUPBAR(g) asm volatile("bar.sync %0, 128;" :: "r"((g) + 3) : "memory")

// gate-pair weights, [m_global (0..63: feat|h)][j] -> {(wi,wf),(wg,wo)}
__constant__ ulonglong2 cW[2048];          // 32 KB
__device__   ulonglong2 g_pack[2048];      // staging for the D2D copy

// smem float offsets (weights no longer in smem)
#define OFF_B   0      // ull2[32] bias pairs (128 floats)
#define OFF_CO  128    // float4[32] coW
#define OFF_CF  256    // float[32*8] cf rows
#define OFF_COB 512
#define OFF_K   516    // 16 runtime Kalman consts
#define OFF_GRP 544
#define GX    0        // [2 buf][8 k][64 el]
#define GFEAT 1024     // [32 m][64 el]
#define GH    3072     // [32 j][64 el]
#define GC    5120     // [32 j][64 el]
#define GRP_FLOATS 7168
#define SMEM_FLOATS (544 + 2 * 7168)

#define KC_GHX 0
#define KC_GHY 3
#define KC_R   6
#define KC_GT  9

extern __shared__ float s_raw[];

// pack Wih/Whh into gate-pair ulonglong2 layout in g_pack
__global__ void pack_weights_kernel(const float* __restrict__ Wih,
                                    const float* __restrict__ Whh)
{
    int idx = blockIdx.x * blockDim.x + threadIdx.x;
    if (idx >= 2048) return;
    int mg = idx >> 5;            // 0..63
    int j  = idx & 31;
    const float* W = (mg < 32) ? Wih : Whh;
    int m = mg & 31;
    ulonglong2 v;
    v.x = pack2(W[j * 32 + m],        W[(32 + j) * 32 + m]);
    v.y = pack2(W[(64 + j) * 32 + m], W[(96 + j) * 32 + m]);
    g_pack[idx] = v;
}

__global__ void __launch_bounds__(TB, 2) kalman_lstm_kernel(
    const float* __restrict__ hist,
    const float* __restrict__ p_psx, const float* __restrict__ p_psy,
    const float* __restrict__ p_vsx, const float* __restrict__ p_vsy,
    const float* __restrict__ p_asx, const float* __restrict__ p_asy,
    const float* __restrict__ p_jerk, const float* __restrict__ p_coefG,
    const float* __restrict__ p_GR,
    const float* __restrict__ cfW, const float* __restrict__ cfb,
    const float* __restrict__ bih, const float* __restrict__ bhh,
    const float* __restrict__ coW, const float* __restrict__ cob,
    float* __restrict__ out,
    int B, int LP)
{
    const int tid = threadIdx.x;
    const int warpid = tid >> 5;
    const int lane = tid & 31;

    // ---- stage small tables/consts ----
    if (tid < 32) {
        int j = tid;
        ulonglong2 b;
        b.x = pack2(bih[j] + bhh[j],           bih[32 + j] + bhh[32 + j]);
        b.y = pack2(bih[64 + j] + bhh[64 + j], bih[96 + j] + bhh[96 + j]);
        reinterpret_cast<ulonglong2*>(s_raw + OFF_B)[j] = b;
        reinterpret_cast<float4*>(s_raw + OFF_CO)[j] = make_float4(
            coW[j], coW[32 + j], coW[64 + j], coW[96 + j]);
#pragma unroll
        for (int k = 0; k < 6; k++) s_raw[OFF_CF + j * 8 + k] = cfW[j * 6 + k];
        s_raw[OFF_CF + j * 8 + 6] = cfb[j];
        s_raw[OFF_CF + j * 8 + 7] = 0.0f;
    }
    if (tid == 32) {
        const float g0 = (float)(0.2 * 0.2 * 0.2 / 6.0), g1 = 0.02f, g2 = 0.2f;
        float tg0 = tanhf(p_coefG[0]), tg1 = tanhf(p_coefG[1]), tg2 = tanhf(p_coefG[2]);
        float tg3 = tanhf(p_coefG[3]), tg4 = tanhf(p_coefG[4]), tg5 = tanhf(p_coefG[5]);
        float jk0 = p_jerk[0], jk1 = p_jerk[1];
        s_raw[OFF_K + KC_GHX + 0] = g0 * tg0 * jk0;
        s_raw[OFF_K + KC_GHX + 1] = g1 * tg1 * jk0;
        s_raw[OFF_K + KC_GHX + 2] = g2 * tg2 * jk0;
        s_raw[OFF_K + KC_GHY + 0] = g0 * tg3 * jk1;
        s_raw[OFF_K + KC_GHY + 1] = g1 * tg4 * jk1;
        s_raw[OFF_K + KC_GHY + 2] = g2 * tg5 * jk1;
        float gr0 = p_GR[0], gr1 = p_GR[1];
        s_raw[OFF_K + KC_R + 0] = gr0 * gr0;
        s_raw[OFF_K + KC_R + 1] = gr0 * gr1;
        s_raw[OFF_K + KC_R + 2] = gr1 * gr1;
        s_raw[OFF_K + KC_GT + 0] = g0 * tg0;
        s_raw[OFF_K + KC_GT + 1] = g1 * tg1;
        s_raw[OFF_K + KC_GT + 2] = g2 * tg2;
        s_raw[OFF_K + KC_GT + 3] = g0 * tg3;
        s_raw[OFF_K + KC_GT + 4] = g1 * tg4;
        s_raw[OFF_K + KC_GT + 5] = g2 * tg5;
        s_raw[OFF_COB + 0] = cob[0]; s_raw[OFF_COB + 1] = cob[1];
        s_raw[OFF_COB + 2] = cob[2]; s_raw[OFF_COB + 3] = cob[3];
    }

    const float dt = 0.2f, hd2 = 0.02f;
    const float g0 = (float)(0.2 * 0.2 * 0.2 / 6.0);
    const float g1 = 0.02f;
    const float g2 = 0.2f;
    const float2* hist2 = reinterpret_cast<const float2*>(hist);

    float X[6], P[6][6];
    int e = 0; bool valid = false;

    if (warpid < 4) {
        const int g = warpid >> 1, w = warpid & 1;
        float* base = s_raw + OFF_GRP + g * GRP_FLOATS;
#pragma unroll
        for (int jj = 0; jj < 16; jj++) {
            int j = w * 16 + jj;
            base[GH + j * 64 + lane] = 0.0f;
            base[GH + j * 64 + 32 + lane] = 0.0f;
            base[GC + j * 64 + lane] = 0.0f;
            base[GC + j * 64 + 32 + lane] = 0.0f;
        }
    } else {
        const int g = (warpid - 4) >> 1, half = (warpid - 4) & 1;
        const int el = half * 32 + lane;
        int e_raw = blockIdx.x * 128 + g * 64 + el;
        valid = e_raw < B;
        e = valid ? e_raw : (B - 1);
        float2 z0 = hist2[e];
        float2 z1 = hist2[(size_t)B + e];
        X[0] = z0.x; X[1] = (z1.x - z0.x) / dt; X[2] = 0.0f;
        X[3] = (z1.y - z0.y) / dt; X[4] = 0.0f; X[5] = 0.0f;
#pragma unroll
        for (int i = 0; i < 6; i++)
#pragma unroll
            for (int j = 0; j < 6; j++) P[i][j] = 0.0f;
        float d0 = p_psx[0], d1 = p_vsx[0], d2 = p_asx[0];
        float d3 = p_psy[0], d4 = p_vsy[0], d5 = p_asy[0];
        P[0][0] = d0 * d0; P[1][1] = d1 * d1; P[2][2] = d2 * d2;
        P[3][3] = d3 * d3; P[4][4] = d4 * d4; P[5][5] = d5 * d5;
        float* xw = s_raw + OFF_GRP + g * GRP_FLOATS + GX;
#pragma unroll
        for (int k = 0; k < 6; k++) xw[k * 64 + el] = X[k];
    }
    __syncthreads();

    if (warpid < 4) {
        // ======================= LSTM warps =======================
        const int g = warpid >> 1, w = warpid & 1;
        float* base = s_raw + OFF_GRP + g * GRP_FLOATS;
        float* FEAT = base + GFEAT;
        float* H    = base + GH;
        float* C    = base + GC;
        const int eA = lane, eB = lane + 32;
        int xb = 0;
        const int TS = 15 + LP;

#pragma unroll 1
        for (int step = 0; step < TS; step++) {
            // ---- feat for my 16 m rows, both elements ----
            {
                const float* xp = base + GX + xb * 512;
                float XA[6], XBv[6];
#pragma unroll
                for (int k = 0; k < 6; k++) {
                    XA[k]  = xp[k * 64 + eA];
                    XBv[k] = xp[k * 64 + eB];
                }
                const float4* cf = reinterpret_cast<const float4*>(s_raw + OFF_CF) + w * 32;
#pragma unroll 2
                for (int k = 0; k < 16; k++) {
                    int m = w * 16 + k;
                    float4 a = cf[0];
                    float4 b = cf[1];
                    cf += 2;
                    float accA = b.z, accB = b.z;
                    accA = fmaf(a.x, XA[0], accA);  accB = fmaf(a.x, XBv[0], accB);
                    accA = fmaf(a.y, XA[1], accA);  accB = fmaf(a.y, XBv[1], accB);
                    accA = fmaf(a.z, XA[2], accA);  accB = fmaf(a.z, XBv[2], accB);
                    accA = fmaf(a.w, XA[3], accA);  accB = fmaf(a.w, XBv[3], accB);
                    accA = fmaf(b.x, XA[4], accA);  accB = fmaf(b.x, XBv[4], accB);
                    accA = fmaf(b.y, XA[5], accA);  accB = fmaf(b.y, XBv[5], accB);
                    FEAT[m * 64 + eA] = ftanh(accA);
                    FEAT[m * 64 + eB] = ftanh(accB);
                }
            }
            PAIRBAR(g);

            // ---- gate passes: 2 passes x 8 j; weights via __constant__ (LDCU/UR) ----
            float hA[16], hB[16];
#pragma unroll 1
            for (int pass = 0; pass < 2; pass++) {
                const int jb = w * 16 + pass * 8;
                ull aifA[8], agoA[8], aifB[8], agoB[8];
                {
                    const ulonglong2* sb = reinterpret_cast<const ulonglong2*>(s_raw + OFF_B) + jb;
#pragma unroll
                    for (int jj = 0; jj < 8; jj++) {
                        ulonglong2 b = sb[jj];
                        aifA[jj] = b.x; agoA[jj] = b.y;
                        aifB[jj] = b.x; agoB[jj] = b.y;
                    }
                }
                const float* fA = FEAT + eA;
                const float* fB = FEAT + eB;
#pragma unroll 4
                for (int m = 0; m < 32; m++) {
                    ull a2A = dup2(fA[m * 64]);
                    ull a2B = dup2(fB[m * 64]);
#pragma unroll
                    for (int jj = 0; jj < 8; jj++) {
                        ulonglong2 ww = cW[m * 32 + jb + jj];
                        FMA2(aifA[jj], ww.x, a2A);
                        FMA2(agoA[jj], ww.y, a2A);
                        FMA2(aifB[jj], ww.x, a2B);
                        FMA2(agoB[jj], ww.y, a2B);
                    }
                }
                const float* hIA = H + eA;
                const float* hIB = H + eB;
#pragma unroll 4
                for (int m = 0; m < 32; m++) {
                    ull a2A = dup2(hIA[m * 64]);
                    ull a2B = dup2(hIB[m * 64]);
#pragma unroll
                    for (int jj = 0; jj < 8; jj++) {
                        ulonglong2 ww = cW[(32 + m) * 32 + jb + jj];
                        FMA2(aifA[jj], ww.x, a2A);
                        FMA2(agoA[jj], ww.y, a2A);
                        FMA2(aifB[jj], ww.x, a2B);
                        FMA2(agoB[jj], ww.y, a2B);
                    }
                }
#pragma unroll
                for (int jj = 0; jj < 8; jj++) {
                    int j = jb + jj;
                    float gi, gf, gg, go;
                    unpack2(aifA[jj], gi, gf);
                    unpack2(agoA[jj], gg, go);
                    float ig = fsig(gi), fg = fsig(gf);
                    float g_ = ftanh(gg), og = fsig(go);
                    float cj = fmaf(fg, C[j * 64 + eA], ig * g_);
                    C[j * 64 + eA] = cj;
                    hA[pass * 8 + jj] = og * ftanh(cj);

                    unpack2(aifB[jj], gi, gf);
                    unpack2(agoB[jj], gg, go);
                    ig = fsig(gi); fg = fsig(gf);
                    g_ = ftanh(gg); og = fsig(go);
                    cj = fmaf(fg, C[j * 64 + eB], ig * g_);
                    C[j * 64 + eB] = cj;
                    hB[pass * 8 + jj] = og * ftanh(cj);
                }
            }
            PAIRBAR(g);

#pragma unroll
            for (int jj = 0; jj < 16; jj++) {
                int j = w * 16 + jj;
                H[j * 64 + eA] = hA[jj];
                H[j * 64 + eB] = hB[jj];
            }

            GROUPBAR(g);
            if (step >= 15) GROUPBAR(g);
            xb ^= 1;
        }
    } else {
        // ======================= Kalman warps =======================
        const int g = (warpid - 4) >> 1, half = (warpid - 4) & 1;
        const int el = half * 32 + lane;
        float* base = s_raw + OFF_GRP + g * GRP_FLOATS;
        const float* KC = s_raw + OFF_K;
        int xb = 0;

        // ---------- history t = 1..15 ----------
#pragma unroll 1
        for (int t = 1; t < 16; t++) {
            {
                float x0 = X[0] + dt * X[1] + hd2 * X[2];
                float x1 = X[1] + dt * X[2];
                float x3 = X[3] + dt * X[4] + hd2 * X[5];
                float x4 = X[4] + dt * X[5];
                X[0] = x0; X[1] = x1; X[3] = x3; X[4] = x4;
            }
#pragma unroll
            for (int cc = 0; cc < 6; cc++) {
                P[0][cc] += dt * P[1][cc] + hd2 * P[2][cc];
                P[1][cc] += dt * P[2][cc];
                P[3][cc] += dt * P[4][cc] + hd2 * P[5][cc];
                P[4][cc] += dt * P[5][cc];
            }
#pragma unroll
            for (int r = 0; r < 6; r++) {
                P[r][0] += dt * P[r][1] + hd2 * P[r][2];
                P[r][1] += dt * P[r][2];
                P[r][3] += dt * P[r][4] + hd2 * P[r][5];
                P[r][4] += dt * P[r][5];
            }
            {
                float gx[3] = {KC[KC_GHX], KC[KC_GHX + 1], KC[KC_GHX + 2]};
                float gy[3] = {KC[KC_GHY], KC[KC_GHY + 1], KC[KC_GHY + 2]};
#pragma unroll
                for (int a = 0; a < 3; a++)
#pragma unroll
                    for (int bb = 0; bb < 3; bb++) {
                        P[a][bb]         += gx[a] * gx[bb];
                        P[3 + a][3 + bb] += gy[a] * gy[bb];
                    }
            }
            float R00 = KC[KC_R], R01 = KC[KC_R + 1], R11 = KC[KC_R + 2];
            float2 z = hist2[(size_t)t * B + e];
            float yx = z.x - X[0], yy = z.y - X[3];
            float S00 = P[0][0] + R00, S01 = P[0][3] + R01;
            float S10 = P[3][0] + R01, S11 = P[3][3] + R11;
            float rdet = 1.0f / (S00 * S11 - S01 * S10);
            float si00 =  S11 * rdet, si01 = -S01 * rdet;
            float si10 = -S10 * rdet, si11 =  S00 * rdet;
            float K0[6], K1[6];
#pragma unroll
            for (int i = 0; i < 6; i++) {
                K0[i] = P[i][0] * si00 + P[i][3] * si10;
                K1[i] = P[i][0] * si01 + P[i][3] * si11;
            }
#pragma unroll
            for (int i = 0; i < 6; i++) X[i] += K0[i] * yx + K1[i] * yy;
            float r0[6], r3[6];
#pragma unroll
            for (int j = 0; j < 6; j++) { r0[j] = P[0][j]; r3[j] = P[3][j]; }
#pragma unroll
            for (int i = 0; i < 6; i++)
#pragma unroll
                for (int j = 0; j < 6; j++) P[i][j] -= K0[i] * r0[j] + K1[i] * r3[j];

            float* xw = base + GX + (xb ^ 1) * 512;
#pragma unroll
            for (int k = 0; k < 6; k++) xw[k * 64 + el] = X[k];
            GROUPBAR(g);
            xb ^= 1;
        }

        // ---------- prediction t = 0..LP-1 ----------
#pragma unroll 1
        for (int t = 0; t < LP; t++) {
            GROUPBAR(g);   // h(t) ready

            float cm0 = s_raw[OFF_COB + 0], cm1 = s_raw[OFF_COB + 1];
            float cm2 = s_raw[OFF_COB + 2], cm3 = s_raw[OFF_COB + 3];
            {
                const float* hb = base + GH + el;
                const float4* co4 = reinterpret_cast<const float4*>(s_raw + OFF_CO);
#pragma unroll 2
                for (int m = 0; m < 32; m++) {
                    float4 cw = co4[m];
                    float hm = hb[m * 64];
                    cm0 = fmaf(cw.x, hm, cm0);
                    cm1 = fmaf(cw.y, hm, cm1);
                    cm2 = fmaf(cw.z, hm, cm2);
                    cm3 = fmaf(cw.w, hm, cm3);
                }
            }
            {
                float x0 = X[0] + dt * X[1] + hd2 * X[2] + g0 * cm0;
                float x1 = X[1] + dt * X[2] + g1 * cm0;
                float x2 = X[2] + g2 * cm0;
                float x3 = X[3] + dt * X[4] + hd2 * X[5] + g0 * cm1;
                float x4 = X[4] + dt * X[5] + g1 * cm1;
                float x5 = X[5] + g2 * cm1;
                X[0] = x0; X[1] = x1; X[2] = x2; X[3] = x3; X[4] = x4; X[5] = x5;
            }
            float Gs[6] = {KC[KC_GT + 0] * cm2, KC[KC_GT + 1] * cm2, KC[KC_GT + 2] * cm2,
                           KC[KC_GT + 3] * cm3, KC[KC_GT + 4] * cm3, KC[KC_GT + 5] * cm3};
#pragma unroll
            for (int cc = 0; cc < 6; cc++) {
                P[0][cc] += dt * P[1][cc] + hd2 * P[2][cc];
                P[1][cc] += dt * P[2][cc];
                P[3][cc] += dt * P[4][cc] + hd2 * P[5][cc];
                P[4][cc] += dt * P[5][cc];
            }
#pragma unroll
            for (int r = 0; r < 6; r++) {
                P[r][0] += dt * P[r][1] + hd2 * P[r][2];
                P[r][1] += dt * P[r][2];
                P[r][3] += dt * P[r][4] + hd2 * P[r][5];
                P[r][4] += dt * P[r][5];
            }
#pragma unroll
            for (int i = 0; i < 6; i++)
#pragma unroll
                for (int j = 0; j < 6; j++) P[i][j] += Gs[i] * Gs[j];

            if (valid) {
                float sx = sqrtf(P[0][0]);
                float sy = sqrtf(P[3][3]);
                float rho = __fdividef(P[0][3] + P[3][0], 2.0f * sx * sy);
                size_t o = ((size_t)t * B + e) * 5;
                out[o + 0] = X[0];
                out[o + 1] = X[3];
                out[o + 2] = sx;
                out[o + 3] = sy;
                out[o + 4] = rho;
            }

            float* xw = base + GX + (xb ^ 1) * 512;
#pragma unroll
            for (int k = 0; k < 6; k++) xw[k * 64 + el] = X[k];
            GROUPBAR(g);   // X ready for next LSTM step
            xb ^= 1;
        }
    }
}

extern "C" void kernel_launch(void* const* d_in, const int* in_sizes, int n_in,
                              void* d_out, int out_size) {
    const float* hist  = (const float*)d_in[0];
    const float* psx   = (const float*)d_in[1];
    const float* psy   = (const float*)d_in[2];
    const float* vsx   = (const float*)d_in[3];
    const float* vsy   = (const float*)d_in[4];
    const float* asx   = (const float*)d_in[5];
    const float* asy   = (const float*)d_in[6];
    const float* jerk  = (const float*)d_in[7];
    const float* coefG = (const float*)d_in[8];
    const float* GR    = (const float*)d_in[9];
    const float* cfW   = (const float*)d_in[10];
    const float* cfb   = (const float*)d_in[11];
    const float* Wih   = (const float*)d_in[12];
    const float* Whh   = (const float*)d_in[13];
    const float* bih   = (const float*)d_in[14];
    const float* bhh   = (const float*)d_in[15];
    const float* coW   = (const float*)d_in[16];
    const float* cob   = (const float*)d_in[17];
    float* out = (float*)d_out;

    const int T = 16;
    int B  = in_sizes[0] / (2 * T);
    int LP = out_size / (B * 5);

    // pack weights -> __device__ scratch, then D2D copy into the constant bank.
    // cudaGetSymbolAddress resolves the DEVICE addresses (host shadow of g_pack
    // is NOT a device pointer — that was the R10 bug).
    pack_weights_kernel<<<8, 256>>>(Wih, Whh);
    void* d_cW = nullptr;
    void* d_gp = nullptr;
    cudaGetSymbolAddress(&d_cW, cW);
    cudaGetSymbolAddress(&d_gp, g_pack);
    cudaMemcpyAsync(d_cW, d_gp, 2048 * sizeof(ulonglong2),
                    cudaMemcpyDeviceToDevice, 0);

    size_t smem = (size_t)SMEM_FLOATS * sizeof(float);  // 59520 bytes
    cudaFuncSetAttribute(kalman_lstm_kernel,
                         cudaFuncAttributeMaxDynamicSharedMemorySize, (int)smem);

    int grid = (B + 127) / 128;
    kalman_lstm_kernel<<<grid, TB, smem>>>(
        hist, psx, psy, vsx, vsy, asx, asy, jerk, coefG, GR,
        cfW, cfb, bih, bhh, coW, cob, out, B, LP);
}

// round 13
// speedup vs baseline: 1.9040x; 1.9040x over previous
#include <cuda_runtime.h>
#include <cstdint>

#define TB  128
#define SA  68        // tile row stride (floats) -> frag LDS conflict-free
#define GP  36        // gbuf col stride (transposed [col][row])
#define CP  33        // c-state stride

// ---- smem float offsets ----
#define OFF_BIAS 0                       // float4[32] (i,f,g,o) per j
#define OFF_CF   128                     // float[32*8]
#define OFF_CO   384                     // float4[32]
#define OFF_COB  512                     // float[4] (+pad to 528)
#define OFF_AB   528                     // act big   [128][SA]
#define OFF_AS   (OFF_AB + 128*SA)       // act small
#define OFF_BB   (OFF_AS + 128*SA)       // weight big [128 n][SA]
#define OFF_BS   (OFF_BB + 128*SA)       // weight small
#define OFF_G    (OFF_BS + 128*SA)       // gbuf: 4 warps x [32 col][GP]
#define OFF_C    (OFF_G + 4*32*GP)       // c:    4 warps x [32 j][CP]
#define SMEM_FLOATS (OFF_C + 4*32*CP)    // 44176 floats = 176704 B

extern __shared__ float s_raw[];

__device__ __forceinline__ float fsig(float x) { float e = __expf(-x); return __fdividef(1.f, 1.f + e); }
__device__ __forceinline__ float ftanh(float x) { float e = __expf(2.f * x); return 1.f - __fdividef(2.f, e + 1.f); }
__device__ __forceinline__ uint32_t tf32b(float f) {
    uint32_t u; asm("cvt.rna.tf32.f32 %0, %1;" : "=r"(u) : "f"(f)); return u;
}
__device__ __forceinline__ void mma8(float* d, const uint32_t* a, uint32_t b0, uint32_t b1) {
    asm volatile(
        "mma.sync.aligned.m16n8k8.row.col.f32.tf32.tf32.f32 "
        "{%0,%1,%2,%3}, {%4,%5,%6,%7}, {%8,%9}, {%0,%1,%2,%3};"
        : "+f"(d[0]), "+f"(d[1]), "+f"(d[2]), "+f"(d[3])
        : "r"(a[0]), "r"(a[1]), "r"(a[2]), "r"(a[3]), "r"(b0), "r"(b1));
}

__global__ void __launch_bounds__(TB, 1) kalman_lstm_kernel(
    const float* __restrict__ hist,
    const float* __restrict__ p_psx, const float* __restrict__ p_psy,
    const float* __restrict__ p_vsx, const float* __restrict__ p_vsy,
    const float* __restrict__ p_asx, const float* __restrict__ p_asy,
    const float* __restrict__ p_jerk, const float* __restrict__ p_coefG,
    const float* __restrict__ p_GR,
    const float* __restrict__ cfW, const float* __restrict__ cfb,
    const float* __restrict__ Wih, const float* __restrict__ Whh,
    const float* __restrict__ bih, const float* __restrict__ bhh,
    const float* __restrict__ coW, const float* __restrict__ cob,
    float* __restrict__ out,
    int B, int LP)
{
    const int tid = threadIdx.x;
    const int w = tid >> 5;
    const int lane = tid & 31;
    const int gr = lane >> 2, tq = lane & 3;
    uint32_t* s_u32 = reinterpret_cast<uint32_t*>(s_raw);

    // ---- small tables ----
    if (tid < 32) {
        int j = tid;
        reinterpret_cast<float4*>(s_raw + OFF_BIAS)[j] = make_float4(
            bih[j] + bhh[j],           bih[32 + j] + bhh[32 + j],
            bih[64 + j] + bhh[64 + j], bih[96 + j] + bhh[96 + j]);
        reinterpret_cast<float4*>(s_raw + OFF_CO)[j] = make_float4(
            coW[j], coW[32 + j], coW[64 + j], coW[96 + j]);
#pragma unroll
        for (int k = 0; k < 6; k++) s_raw[OFF_CF + j * 8 + k] = cfW[j * 6 + k];
        s_raw[OFF_CF + j * 8 + 6] = cfb[j];
        s_raw[OFF_CF + j * 8 + 7] = 0.0f;
    }
    if (tid == 32) {
        s_raw[OFF_COB + 0] = cob[0]; s_raw[OFF_COB + 1] = cob[1];
        s_raw[OFF_COB + 2] = cob[2]; s_raw[OFF_COB + 3] = cob[3];
    }

    // ---- weight tiles: row n = 32*chunk + 4*q + gate ; j = 8*chunk + q ----
    {
        int n = tid;
        int gate = n & 3, q = (n >> 2) & 7, ch = n >> 5;
        int j = ch * 8 + q;
        const float* wi = Wih + (gate * 32 + j) * 32;
        const float* wh = Whh + (gate * 32 + j) * 32;
#pragma unroll 4
        for (int k = 0; k < 64; k++) {
            float wv = (k < 32) ? wi[k] : wh[k - 32];
            uint32_t bg = tf32b(wv);
            float resid = wv - __uint_as_float(bg);
            s_u32[OFF_BB + n * SA + k] = bg;
            s_u32[OFF_BS + n * SA + k] = tf32b(resid);
        }
    }
    // zero act tiles (both) and c-state
    for (int i = tid; i < 2 * 128 * SA; i += TB) s_raw[OFF_AB + i] = 0.0f;
    for (int i = tid; i < 4 * 32 * CP;  i += TB) s_raw[OFF_C + i] = 0.0f;
    __syncthreads();

    // ---- per-thread Kalman state ----
    const float dt = 0.2f, hd2 = 0.02f;
    const float g0 = (float)(0.2 * 0.2 * 0.2 / 6.0), g1 = 0.02f, g2 = 0.2f;
    const int el = tid;                                 // element row within CTA
    const int e_raw = blockIdx.x * TB + tid;
    const bool valid = e_raw < B;
    const int e = valid ? e_raw : (B - 1);
    const float2* hist2 = reinterpret_cast<const float2*>(hist);

    float tg[6];
#pragma unroll
    for (int i = 0; i < 6; i++) tg[i] = tanhf(p_coefG[i]);
    const float jk0 = p_jerk[0], jk1 = p_jerk[1];
    const float Ghx0 = g0 * tg[0] * jk0, Ghx1 = g1 * tg[1] * jk0, Ghx2 = g2 * tg[2] * jk0;
    const float Ghy0 = g0 * tg[3] * jk1, Ghy1 = g1 * tg[4] * jk1, Ghy2 = g2 * tg[5] * jk1;
    const float gt0 = g0 * tg[0], gt1 = g1 * tg[1], gt2 = g2 * tg[2];
    const float gt3 = g0 * tg[3], gt4 = g1 * tg[4], gt5 = g2 * tg[5];
    const float gr0_ = p_GR[0], gr1_ = p_GR[1];
    const float R00 = gr0_ * gr0_, R01 = gr0_ * gr1_, R11 = gr1_ * gr1_;

    float2 z0 = hist2[e];
    float2 z1 = hist2[(size_t)B + e];
    float X[6];
    X[0] = z0.x; X[1] = (z1.x - z0.x) / dt; X[2] = 0.0f;
    X[3] = (z1.y - z0.y) / dt; X[4] = 0.0f; X[5] = 0.0f;
    float P[6][6];
#pragma unroll
    for (int i = 0; i < 6; i++)
#pragma unroll
        for (int j = 0; j < 6; j++) P[i][j] = 0.0f;
    {
        float d0 = p_psx[0], d1 = p_vsx[0], d2 = p_asx[0];
        float d3 = p_psy[0], d4 = p_vsy[0], d5 = p_asy[0];
        P[0][0] = d0 * d0; P[1][1] = d1 * d1; P[2][2] = d2 * d2;
        P[3][3] = d3 * d3; P[4][4] = d4 * d4; P[5][5] = d5 * d5;
    }

    const int rbase = w * 32;
    float* gw = s_raw + OFF_G + w * 32 * GP;
    float* cw = s_raw + OFF_C + w * 32 * CP;
    const int TS = 15 + LP;

#pragma unroll 1
    for (int step = 0; step < TS; step++) {
        // ---- feat -> act tiles k=0..31 (big/small) ----
        {
            const float4* cf = reinterpret_cast<const float4*>(s_raw + OFF_CF);
#pragma unroll
            for (int m0 = 0; m0 < 32; m0 += 4) {
                uint4 vb, vs;
                uint32_t* pb = &vb.x; uint32_t* ps = &vs.x;
#pragma unroll
                for (int qq = 0; qq < 4; qq++) {
                    float4 a = cf[(m0 + qq) * 2];
                    float4 b = cf[(m0 + qq) * 2 + 1];
                    float acc = b.z;
                    acc = fmaf(a.x, X[0], acc);
                    acc = fmaf(a.y, X[1], acc);
                    acc = fmaf(a.z, X[2], acc);
                    acc = fmaf(a.w, X[3], acc);
                    acc = fmaf(b.x, X[4], acc);
                    acc = fmaf(b.y, X[5], acc);
                    float f = ftanh(acc);
                    uint32_t bg = tf32b(f);
                    pb[qq] = bg;
                    ps[qq] = tf32b(f - __uint_as_float(bg));
                }
                *reinterpret_cast<uint4*>(s_u32 + OFF_AB + el * SA + m0) = vb;
                *reinterpret_cast<uint4*>(s_u32 + OFF_AS + el * SA + m0) = vs;
            }
        }
        __syncwarp();

        // ---- load big-A fragments (kept across chunks) ----
        uint32_t ab[2][8][4];
#pragma unroll
        for (int mt = 0; mt < 2; mt++) {
#pragma unroll
            for (int kt = 0; kt < 8; kt++) {
                int r = OFF_AB + (rbase + mt * 16 + gr) * SA + kt * 8 + tq;
                ab[mt][kt][0] = s_u32[r];
                ab[mt][kt][1] = s_u32[r + 8 * SA];
                ab[mt][kt][2] = s_u32[r + 4];
                ab[mt][kt][3] = s_u32[r + 8 * SA + 4];
            }
        }

        float cm0 = s_raw[OFF_COB + 0], cm1 = s_raw[OFF_COB + 1];
        float cm2 = s_raw[OFF_COB + 2], cm3 = s_raw[OFF_COB + 3];

#pragma unroll 1
        for (int chunk = 0; chunk < 4; chunk++) {
            float d[2][4][4];
#pragma unroll
            for (int mt = 0; mt < 2; mt++)
#pragma unroll
                for (int nt = 0; nt < 4; nt++)
#pragma unroll
                    for (int k4 = 0; k4 < 4; k4++) d[mt][nt][k4] = 0.0f;

            const int bbase = (chunk * 32 + gr) * SA + tq;
#pragma unroll
            for (int kt = 0; kt < 8; kt++) {
                // small-A fragments for this kt
                uint32_t as0[4], as1[4];
                {
                    int r = OFF_AS + (rbase + gr) * SA + kt * 8 + tq;
                    as0[0] = s_u32[r];          as0[1] = s_u32[r + 8 * SA];
                    as0[2] = s_u32[r + 4];      as0[3] = s_u32[r + 8 * SA + 4];
                    r += 16 * SA;
                    as1[0] = s_u32[r];          as1[1] = s_u32[r + 8 * SA];
                    as1[2] = s_u32[r + 4];      as1[3] = s_u32[r + 8 * SA + 4];
                }
#pragma unroll
                for (int nt = 0; nt < 4; nt++) {
                    int bi = bbase + nt * 8 * SA + kt * 8;
                    uint32_t bb0 = s_u32[OFF_BB + bi];
                    uint32_t bb1 = s_u32[OFF_BB + bi + 4];
                    uint32_t bs0 = s_u32[OFF_BS + bi];
                    uint32_t bs1 = s_u32[OFF_BS + bi + 4];
                    mma8(d[0][nt], ab[0][kt], bb0, bb1);
                    mma8(d[0][nt], as0,       bb0, bb1);
                    mma8(d[0][nt], ab[0][kt], bs0, bs1);
                    mma8(d[1][nt], ab[1][kt], bb0, bb1);
                    mma8(d[1][nt], as1,       bb0, bb1);
                    mma8(d[1][nt], ab[1][kt], bs0, bs1);
                }
            }

            // ---- store D transposed: gw[col][row] ----
#pragma unroll
            for (int mt = 0; mt < 2; mt++)
#pragma unroll
                for (int nt = 0; nt < 4; nt++) {
                    int r0 = mt * 16 + gr, r1 = r0 + 8;
                    int c0 = nt * 8 + 2 * tq, c1 = c0 + 1;
                    gw[c0 * GP + r0] = d[mt][nt][0];
                    gw[c1 * GP + r0] = d[mt][nt][1];
                    gw[c0 * GP + r1] = d[mt][nt][2];
                    gw[c1 * GP + r1] = d[mt][nt][3];
                }
            __syncwarp();

            // ---- epilogue: 8 j's of this chunk for my own element ----
            uint32_t hb[8], hs[8];
            const float4* bias4 = reinterpret_cast<const float4*>(s_raw + OFF_BIAS);
            const float4* co4   = reinterpret_cast<const float4*>(s_raw + OFF_CO);
#pragma unroll
            for (int q = 0; q < 8; q++) {
                int j = chunk * 8 + q;
                float gi = gw[(4 * q + 0) * GP + lane];
                float gf = gw[(4 * q + 1) * GP + lane];
                float gg = gw[(4 * q + 2) * GP + lane];
                float go = gw[(4 * q + 3) * GP + lane];
                float4 bq = bias4[j];
                gi += bq.x; gf += bq.y; gg += bq.z; go += bq.w;
                float cold = cw[j * CP + lane];
                float cj = fmaf(fsig(gf), cold, fsig(gi) * ftanh(gg));
                cw[j * CP + lane] = cj;
                float h = fsig(go) * ftanh(cj);
                uint32_t bg = tf32b(h);
                hb[q] = bg;
                hs[q] = tf32b(h - __uint_as_float(bg));
                float4 cwt = co4[j];
                cm0 = fmaf(cwt.x, h, cm0);
                cm1 = fmaf(cwt.y, h, cm1);
                cm2 = fmaf(cwt.z, h, cm2);
                cm3 = fmaf(cwt.w, h, cm3);
            }
            // h -> act tiles k = 32 + chunk*8 .. +7
            {
                uint4 v0 = make_uint4(hb[0], hb[1], hb[2], hb[3]);
                uint4 v1 = make_uint4(hb[4], hb[5], hb[6], hb[7]);
                uint4 s0 = make_uint4(hs[0], hs[1], hs[2], hs[3]);
                uint4 s1 = make_uint4(hs[4], hs[5], hs[6], hs[7]);
                uint4* db = reinterpret_cast<uint4*>(s_u32 + OFF_AB + el * SA + 32 + chunk * 8);
                uint4* ds = reinterpret_cast<uint4*>(s_u32 + OFF_AS + el * SA + 32 + chunk * 8);
                db[0] = v0; db[1] = v1;
                ds[0] = s0; ds[1] = s1;
            }
            __syncwarp();
        }

        // ================= Kalman (per-thread fp32) =================
        if (step < 15) {
            int t = step + 1;
            float x0 = X[0] + dt * X[1] + hd2 * X[2];
            float x1 = X[1] + dt * X[2];
            float x3 = X[3] + dt * X[4] + hd2 * X[5];
            float x4 = X[4] + dt * X[5];
            X[0] = x0; X[1] = x1; X[3] = x3; X[4] = x4;
#pragma unroll
            for (int ccx = 0; ccx < 6; ccx++) {
                P[0][ccx] += dt * P[1][ccx] + hd2 * P[2][ccx];
                P[1][ccx] += dt * P[2][ccx];
                P[3][ccx] += dt * P[4][ccx] + hd2 * P[5][ccx];
                P[4][ccx] += dt * P[5][ccx];
            }
#pragma unroll
            for (int rr = 0; rr < 6; rr++) {
                P[rr][0] += dt * P[rr][1] + hd2 * P[rr][2];
                P[rr][1] += dt * P[rr][2];
                P[rr][3] += dt * P[rr][4] + hd2 * P[rr][5];
                P[rr][4] += dt * P[rr][5];
            }
            {
                float gx[3] = {Ghx0, Ghx1, Ghx2}, gy[3] = {Ghy0, Ghy1, Ghy2};
#pragma unroll
                for (int a = 0; a < 3; a++)
#pragma unroll
                    for (int bb = 0; bb < 3; bb++) {
                        P[a][bb]         += gx[a] * gx[bb];
                        P[3 + a][3 + bb] += gy[a] * gy[bb];
                    }
            }
            float2 z = hist2[(size_t)t * B + e];
            float yx = z.x - X[0], yy = z.y - X[3];
            float S00 = P[0][0] + R00, S01 = P[0][3] + R01;
            float S10 = P[3][0] + R01, S11 = P[3][3] + R11;
            float rdet = 1.0f / (S00 * S11 - S01 * S10);
            float si00 =  S11 * rdet, si01 = -S01 * rdet;
            float si10 = -S10 * rdet, si11 =  S00 * rdet;
            float K0[6], K1[6];
#pragma unroll
            for (int i = 0; i < 6; i++) {
                K0[i] = P[i][0] * si00 + P[i][3] * si10;
                K1[i] = P[i][0] * si01 + P[i][3] * si11;
            }
#pragma unroll
            for (int i = 0; i < 6; i++) X[i] += K0[i] * yx + K1[i] * yy;
            float r0[6], r3[6];
#pragma unroll
            for (int j = 0; j < 6; j++) { r0[j] = P[0][j]; r3[j] = P[3][j]; }
#pragma unroll
            for (int i = 0; i < 6; i++)
#pragma unroll
                for (int j = 0; j < 6; j++) P[i][j] -= K0[i] * r0[j] + K1[i] * r3[j];
        } else {
            int t = step - 15;
            float x0 = X[0] + dt * X[1] + hd2 * X[2] + g0 * cm0;
            float x1 = X[1] + dt * X[2] + g1 * cm0;
            float x2 = X[2] + g2 * cm0;
            float x3 = X[3] + dt * X[4] + hd2 * X[5] + g0 * cm1;
            float x4 = X[4] + dt * X[5] + g1 * cm1;
            float x5 = X[5] + g2 * cm1;
            X[0] = x0; X[1] = x1; X[2] = x2; X[3] = x3; X[4] = x4; X[5] = x5;
            float Gs[6] = {gt0 * cm2, gt1 * cm2, gt2 * cm2, gt3 * cm3, gt4 * cm3, gt5 * cm3};
#pragma unroll
            for (int ccx = 0; ccx < 6; ccx++) {
                P[0][ccx] += dt * P[1][ccx] + hd2 * P[2][ccx];
                P[1][ccx] += dt * P[2][ccx];
                P[3][ccx] += dt * P[4][ccx] + hd2 * P[5][ccx];
                P[4][ccx] += dt * P[5][ccx];
            }
#pragma unroll
            for (int rr = 0; rr < 6; rr++) {
                P[rr][0] += dt * P[rr][1] + hd2 * P[rr][2];
                P[rr][1] += dt * P[rr][2];
                P[rr][3] += dt * P[rr][4] + hd2 * P[rr][5];
                P[rr][4] += dt * P[rr][5];
            }
#pragma unroll
            for (int i = 0; i < 6; i++)
#pragma unroll
                for (int j = 0; j < 6; j++) P[i][j] += Gs[i] * Gs[j];

            if (valid) {
                float sx = sqrtf(P[0][0]);
                float sy = sqrtf(P[3][3]);
                float rho = __fdividef(P[0][3] + P[3][0], 2.0f * sx * sy);
                size_t o = ((size_t)t * B + e) * 5;
                out[o + 0] = X[0];
                out[o + 1] = X[3];
                out[o + 2] = sx;
                out[o + 3] = sy;
                out[o + 4] = rho;
            }
        }
    }
}

extern "C" void kernel_launch(void* const* d_in, const int* in_sizes, int n_in,
                              void* d_out, int out_size) {
    const float* hist  = (const float*)d_in[0];
    const float* psx   = (const float*)d_in[1];
    const float* psy   = (const float*)d_in[2];
    const float* vsx   = (const float*)d_in[3];
    const float* vsy   = (const float*)d_in[4];
    const float* asx   = (const float*)d_in[5];
    const float* asy   = (const float*)d_in[6];
    const float* jerk  = (const float*)d_in[7];
    const float* coefG = (const float*)d_in[8];
    const float* GR    = (const float*)d_in[9];
    const float* cfW   = (const float*)d_in[10];
    const float* cfb   = (const float*)d_in[11];
    const float* Wih   = (const float*)d_in[12];
    const float* Whh   = (const float*)d_in[13];
    const float* bih   = (const float*)d_in[14];
    const float* bhh   = (const float*)d_in[15];
    const float* coW   = (const float*)d_in[16];
    const float* cob   = (const float*)d_in[17];
    float* out = (float*)d_out;

    const int T = 16;
    int B  = in_sizes[0] / (2 * T);
    int LP = out_size / (B * 5);

    size_t smem = (size_t)SMEM_FLOATS * sizeof(float);  // 176704 bytes
    cudaFuncSetAttribute(kalman_lstm_kernel,
                         cudaFuncAttributeMaxDynamicSharedMemorySize, (int)smem);

    int grid = (B + TB - 1) / TB;
    kalman_lstm_kernel<<<grid, TB, smem>>>(
        hist, psx, psy, vsx, vsy, asx, asy, jerk, coefG, GR,
        cfW, cfb, Wih, Whh, bih, bhh, coW, cob, out, B, LP);
}

// round 14
// speedup vs baseline: 2.0343x; 1.0685x over previous
#include <cuda_runtime.h>
#include <cstdint>

#define TB  256
#define EL  128       // elements per CTA
#define SA  68        // act/weight tile row stride (floats)
#define GS  132       // gbuf col stride

// ---- smem float offsets ----
#define OFF_BIAS 0                      // float4[32]
#define OFF_CF   128                    // float[32*8]
#define OFF_CO   384                    // float4[32]
#define OFF_COB  512                    // float[4] (+pad)
#define OFF_AB   528
#define OFF_AS   (OFF_AB + 128*SA)
#define OFF_BB   (OFF_AS + 128*SA)
#define OFF_BS   (OFF_BB + 128*SA)
#define OFF_G    (OFF_BS + 128*SA)      // [32 col][GS]
#define OFF_CMD  (OFF_G + 32*GS)        // [2 half][4 q][128 el]
#define SMEM_FLOATS (OFF_CMD + 1024)    // 40592 floats = 162368 B

extern __shared__ float s_raw[];

__device__ __forceinline__ float fsig(float x) { float e = __expf(-x); return __fdividef(1.f, 1.f + e); }
__device__ __forceinline__ float ftanh(float x) { float e = __expf(2.f * x); return 1.f - __fdividef(2.f, e + 1.f); }
__device__ __forceinline__ uint32_t tf32b(float f) {
    uint32_t u; asm("cvt.rna.tf32.f32 %0, %1;" : "=r"(u) : "f"(f)); return u;
}
__device__ __forceinline__ void mma8(float* d, const uint32_t* a, uint32_t b0, uint32_t b1) {
    asm volatile(
        "mma.sync.aligned.m16n8k8.row.col.f32.tf32.tf32.f32 "
        "{%0,%1,%2,%3}, {%4,%5,%6,%7}, {%8,%9}, {%0,%1,%2,%3};"
        : "+f"(d[0]), "+f"(d[1]), "+f"(d[2]), "+f"(d[3])
        : "r"(a[0]), "r"(a[1]), "r"(a[2]), "r"(a[3]), "r"(b0), "r"(b1));
}

__global__ void __launch_bounds__(TB, 1) kalman_lstm_kernel(
    const float* __restrict__ hist,
    const float* __restrict__ p_psx, const float* __restrict__ p_psy,
    const float* __restrict__ p_vsx, const float* __restrict__ p_vsy,
    const float* __restrict__ p_asx, const float* __restrict__ p_asy,
    const float* __restrict__ p_jerk, const float* __restrict__ p_coefG,
    const float* __restrict__ p_GR,
    const float* __restrict__ cfW, const float* __restrict__ cfb,
    const float* __restrict__ Wih, const float* __restrict__ Whh,
    const float* __restrict__ bih, const float* __restrict__ bhh,
    const float* __restrict__ coW, const float* __restrict__ cob,
    float* __restrict__ out,
    int B, int LP)
{
    const int tid = threadIdx.x;
    const int w = tid >> 5;
    const int lane = tid & 31;
    const int gr = lane >> 2, tq = lane & 3;
    const int el = tid & 127;          // element row
    const int jh = tid >> 7;           // j-half (0: j 0..3 per chunk base, 1: j 4..7)
    uint32_t* s_u32 = reinterpret_cast<uint32_t*>(s_raw);

    // ---- small tables ----
    if (tid < 32) {
        int j = tid;
        reinterpret_cast<float4*>(s_raw + OFF_BIAS)[j] = make_float4(
            bih[j] + bhh[j],           bih[32 + j] + bhh[32 + j],
            bih[64 + j] + bhh[64 + j], bih[96 + j] + bhh[96 + j]);
        reinterpret_cast<float4*>(s_raw + OFF_CO)[j] = make_float4(
            coW[j], coW[32 + j], coW[64 + j], coW[96 + j]);
#pragma unroll
        for (int k = 0; k < 6; k++) s_raw[OFF_CF + j * 8 + k] = cfW[j * 6 + k];
        s_raw[OFF_CF + j * 8 + 6] = cfb[j];
        s_raw[OFF_CF + j * 8 + 7] = 0.0f;
    }
    if (tid == 32) {
        s_raw[OFF_COB + 0] = cob[0]; s_raw[OFF_COB + 1] = cob[1];
        s_raw[OFF_COB + 2] = cob[2]; s_raw[OFF_COB + 3] = cob[3];
    }

    // ---- weight tiles: row n = 32*chunk + 4*q + gate ; j = 8*chunk + q ----
    {
        int n = tid & 127;
        int gate = n & 3, q = (n >> 2) & 7, ch = n >> 5;
        int j = ch * 8 + q;
        const float* wi = Wih + (gate * 32 + j) * 32;
        const float* wh = Whh + (gate * 32 + j) * 32;
        int k0 = jh * 32;
#pragma unroll 4
        for (int kk = 0; kk < 32; kk++) {
            int k = k0 + kk;
            float wv = (k < 32) ? wi[k] : wh[k - 32];
            uint32_t bg = tf32b(wv);
            float resid = wv - __uint_as_float(bg);
            s_u32[OFF_BB + n * SA + k] = bg;
            s_u32[OFF_BS + n * SA + k] = tf32b(resid);
        }
    }
    // zero act tiles
    for (int i = tid; i < 2 * 128 * SA; i += TB) s_raw[OFF_AB + i] = 0.0f;
    __syncthreads();

    // ---- per-thread Kalman (duplicated across jh halves) ----
    const float dt = 0.2f, hd2 = 0.02f;
    const float g0 = (float)(0.2 * 0.2 * 0.2 / 6.0), g1 = 0.02f, g2 = 0.2f;
    const int e_raw = blockIdx.x * EL + el;
    const bool valid = e_raw < B;
    const int e = valid ? e_raw : (B - 1);
    const float2* hist2 = reinterpret_cast<const float2*>(hist);

    float tg[6];
#pragma unroll
    for (int i = 0; i < 6; i++) tg[i] = tanhf(p_coefG[i]);
    const float jk0 = p_jerk[0], jk1 = p_jerk[1];
    const float Ghx0 = g0 * tg[0] * jk0, Ghx1 = g1 * tg[1] * jk0, Ghx2 = g2 * tg[2] * jk0;
    const float Ghy0 = g0 * tg[3] * jk1, Ghy1 = g1 * tg[4] * jk1, Ghy2 = g2 * tg[5] * jk1;
    const float gt0 = g0 * tg[0], gt1 = g1 * tg[1], gt2 = g2 * tg[2];
    const float gt3 = g0 * tg[3], gt4 = g1 * tg[4], gt5 = g2 * tg[5];
    const float gr0_ = p_GR[0], gr1_ = p_GR[1];
    const float R00 = gr0_ * gr0_, R01 = gr0_ * gr1_, R11 = gr1_ * gr1_;

    float2 z0 = hist2[e];
    float2 z1 = hist2[(size_t)B + e];
    float X[6];
    X[0] = z0.x; X[1] = (z1.x - z0.x) / dt; X[2] = 0.0f;
    X[3] = (z1.y - z0.y) / dt; X[4] = 0.0f; X[5] = 0.0f;
    float P[6][6];
#pragma unroll
    for (int i = 0; i < 6; i++)
#pragma unroll
        for (int j = 0; j < 6; j++) P[i][j] = 0.0f;
    {
        float d0 = p_psx[0], d1 = p_vsx[0], d2 = p_asx[0];
        float d3 = p_psy[0], d4 = p_vsy[0], d5 = p_asy[0];
        P[0][0] = d0 * d0; P[1][1] = d1 * d1; P[2][2] = d2 * d2;
        P[3][3] = d3 * d3; P[4][4] = d4 * d4; P[5][5] = d5 * d5;
    }
    float creg[16];
#pragma unroll
    for (int j = 0; j < 16; j++) creg[j] = 0.0f;

    const int rb = w * 16;             // my m-tile rows
    float* G = s_raw + OFF_G;
    const int TS = 15 + LP;

#pragma unroll 1
    for (int step = 0; step < TS; step++) {
        // ---- feat: my 16 m rows (m = jh*16 + 0..15) -> A tiles k=jh*16.. ----
        {
            const float4* cf = reinterpret_cast<const float4*>(s_raw + OFF_CF);
#pragma unroll
            for (int m0 = 0; m0 < 16; m0 += 4) {
                uint4 vb, vs;
                uint32_t* pb = &vb.x; uint32_t* ps = &vs.x;
#pragma unroll
                for (int qq = 0; qq < 4; qq++) {
                    int m = jh * 16 + m0 + qq;
                    float4 a = cf[m * 2];
                    float4 b = cf[m * 2 + 1];
                    float acc = b.z;
                    acc = fmaf(a.x, X[0], acc);
                    acc = fmaf(a.y, X[1], acc);
                    acc = fmaf(a.z, X[2], acc);
                    acc = fmaf(a.w, X[3], acc);
                    acc = fmaf(b.x, X[4], acc);
                    acc = fmaf(b.y, X[5], acc);
                    float f = ftanh(acc);
                    uint32_t bg = tf32b(f);
                    pb[qq] = bg;
                    ps[qq] = tf32b(f - __uint_as_float(bg));
                }
                int k = jh * 16 + m0;
                *reinterpret_cast<uint4*>(s_u32 + OFF_AB + el * SA + k) = vb;
                *reinterpret_cast<uint4*>(s_u32 + OFF_AS + el * SA + k) = vs;
            }
        }
        __syncthreads();

        // ---- big-A fragments for my m-tile (all k) ----
        uint32_t ab[8][4];
#pragma unroll
        for (int kt = 0; kt < 8; kt++) {
            int r = OFF_AB + (rb + gr) * SA + kt * 8 + tq;
            ab[kt][0] = s_u32[r];
            ab[kt][1] = s_u32[r + 8 * SA];
            ab[kt][2] = s_u32[r + 4];
            ab[kt][3] = s_u32[r + 8 * SA + 4];
        }

        float cm0 = 0.f, cm1 = 0.f, cm2 = 0.f, cm3 = 0.f;
        uint32_t hbq[4][4], hsq[4][4];

#pragma unroll 1
        for (int chunk = 0; chunk < 4; chunk++) {
            float d[4][4];
#pragma unroll
            for (int nt = 0; nt < 4; nt++)
#pragma unroll
                for (int k4 = 0; k4 < 4; k4++) d[nt][k4] = 0.0f;

            const int bbase = (chunk * 32 + gr) * SA + tq;
#pragma unroll
            for (int kt = 0; kt < 8; kt++) {
                uint32_t as[4];
                {
                    int r = OFF_AS + (rb + gr) * SA + kt * 8 + tq;
                    as[0] = s_u32[r];       as[1] = s_u32[r + 8 * SA];
                    as[2] = s_u32[r + 4];   as[3] = s_u32[r + 8 * SA + 4];
                }
#pragma unroll
                for (int nt = 0; nt < 4; nt++) {
                    int bi = bbase + nt * 8 * SA + kt * 8;
                    uint32_t bb0 = s_u32[OFF_BB + bi];
                    uint32_t bb1 = s_u32[OFF_BB + bi + 4];
                    uint32_t bs0 = s_u32[OFF_BS + bi];
                    uint32_t bs1 = s_u32[OFF_BS + bi + 4];
                    mma8(d[nt], ab[kt], bb0, bb1);
                    mma8(d[nt], as,     bb0, bb1);
                    mma8(d[nt], ab[kt], bs0, bs1);
                }
            }

            __syncthreads();   // previous chunk's epilogue reads of G are done
            // ---- store D transposed into shared gbuf: G[col][row] ----
#pragma unroll
            for (int nt = 0; nt < 4; nt++) {
                int r0 = rb + gr, r1 = r0 + 8;
                int c0 = nt * 8 + 2 * tq, c1 = c0 + 1;
                G[c0 * GS + r0] = d[nt][0];
                G[c1 * GS + r0] = d[nt][1];
                G[c0 * GS + r1] = d[nt][2];
                G[c1 * GS + r1] = d[nt][3];
            }
            __syncthreads();   // gbuf complete

            // ---- epilogue: my 4 j's of this chunk for my element ----
            const float4* bias4 = reinterpret_cast<const float4*>(s_raw + OFF_BIAS);
            const float4* co4   = reinterpret_cast<const float4*>(s_raw + OFF_CO);
#pragma unroll
            for (int q = 0; q < 4; q++) {
                int jn = jh * 4 + q;           // j within chunk (0..7)
                int j  = chunk * 8 + jn;       // global j
                float gi = G[(4 * jn + 0) * GS + el];
                float gf = G[(4 * jn + 1) * GS + el];
                float gg = G[(4 * jn + 2) * GS + el];
                float go = G[(4 * jn + 3) * GS + el];
                float4 bq = bias4[j];
                gi += bq.x; gf += bq.y; gg += bq.z; go += bq.w;
                float cold = creg[chunk * 4 + q];
                float cj = fmaf(fsig(gf), cold, fsig(gi) * ftanh(gg));
                creg[chunk * 4 + q] = cj;
                float h = fsig(go) * ftanh(cj);
                uint32_t bg = tf32b(h);
                hbq[chunk][q] = bg;
                hsq[chunk][q] = tf32b(h - __uint_as_float(bg));
                float4 cwt = co4[j];
                cm0 = fmaf(cwt.x, h, cm0);
                cm1 = fmaf(cwt.y, h, cm1);
                cm2 = fmaf(cwt.z, h, cm2);
                cm3 = fmaf(cwt.w, h, cm3);
            }
        }

        // ---- write h(t) to A tiles (deferred: all chunks read h(t-1)) ----
#pragma unroll
        for (int c = 0; c < 4; c++) {
            int k = 32 + c * 8 + jh * 4;
            *reinterpret_cast<uint4*>(s_u32 + OFF_AB + el * SA + k) =
                make_uint4(hbq[c][0], hbq[c][1], hbq[c][2], hbq[c][3]);
            *reinterpret_cast<uint4*>(s_u32 + OFF_AS + el * SA + k) =
                make_uint4(hsq[c][0], hsq[c][1], hsq[c][2], hsq[c][3]);
        }

        // ================= Kalman (per-thread fp32, duplicated per half) ====
        if (step < 15) {
            int t = step + 1;
            float x0 = X[0] + dt * X[1] + hd2 * X[2];
            float x1 = X[1] + dt * X[2];
            float x3 = X[3] + dt * X[4] + hd2 * X[5];
            float x4 = X[4] + dt * X[5];
            X[0] = x0; X[1] = x1; X[3] = x3; X[4] = x4;
#pragma unroll
            for (int ccx = 0; ccx < 6; ccx++) {
                P[0][ccx] += dt * P[1][ccx] + hd2 * P[2][ccx];
                P[1][ccx] += dt * P[2][ccx];
                P[3][ccx] += dt * P[4][ccx] + hd2 * P[5][ccx];
                P[4][ccx] += dt * P[5][ccx];
            }
#pragma unroll
            for (int rr = 0; rr < 6; rr++) {
                P[rr][0] += dt * P[rr][1] + hd2 * P[rr][2];
                P[rr][1] += dt * P[rr][2];
                P[rr][3] += dt * P[rr][4] + hd2 * P[rr][5];
                P[rr][4] += dt * P[rr][5];
            }
            {
                float gx[3] = {Ghx0, Ghx1, Ghx2}, gy[3] = {Ghy0, Ghy1, Ghy2};
#pragma unroll
                for (int a = 0; a < 3; a++)
#pragma unroll
                    for (int bb = 0; bb < 3; bb++) {
                        P[a][bb]         += gx[a] * gx[bb];
                        P[3 + a][3 + bb] += gy[a] * gy[bb];
                    }
            }
            float2 z = hist2[(size_t)t * B + e];
            float yx = z.x - X[0], yy = z.y - X[3];
            float S00 = P[0][0] + R00, S01 = P[0][3] + R01;
            float S10 = P[3][0] + R01, S11 = P[3][3] + R11;
            float rdet = 1.0f / (S00 * S11 - S01 * S10);
            float si00 =  S11 * rdet, si01 = -S01 * rdet;
            float si10 = -S10 * rdet, si11 =  S00 * rdet;
            float K0[6], K1[6];
#pragma unroll
            for (int i = 0; i < 6; i++) {
                K0[i] = P[i][0] * si00 + P[i][3] * si10;
                K1[i] = P[i][0] * si01 + P[i][3] * si11;
            }
#pragma unroll
            for (int i = 0; i < 6; i++) X[i] += K0[i] * yx + K1[i] * yy;
            float r0[6], r3[6];
#pragma unroll
            for (int j = 0; j < 6; j++) { r0[j] = P[0][j]; r3[j] = P[3][j]; }
#pragma unroll
            for (int i = 0; i < 6; i++)
#pragma unroll
                for (int j = 0; j < 6; j++) P[i][j] -= K0[i] * r0[j] + K1[i] * r3[j];
        } else {
            int t = step - 15;
            // reduce command partials across the two j-halves
            float* CM = s_raw + OFF_CMD;
            CM[jh * 512 + 0 * 128 + el] = cm0;
            CM[jh * 512 + 1 * 128 + el] = cm1;
            CM[jh * 512 + 2 * 128 + el] = cm2;
            CM[jh * 512 + 3 * 128 + el] = cm3;
            __syncthreads();
            float fm0 = CM[0 * 128 + el] + CM[512 + 0 * 128 + el] + s_raw[OFF_COB + 0];
            float fm1 = CM[1 * 128 + el] + CM[512 + 1 * 128 + el] + s_raw[OFF_COB + 1];
            float fm2 = CM[2 * 128 + el] + CM[512 + 2 * 128 + el] + s_raw[OFF_COB + 2];
            float fm3 = CM[3 * 128 + el] + CM[512 + 3 * 128 + el] + s_raw[OFF_COB + 3];

            float x0 = X[0] + dt * X[1] + hd2 * X[2] + g0 * fm0;
            float x1 = X[1] + dt * X[2] + g1 * fm0;
            float x2 = X[2] + g2 * fm0;
            float x3 = X[3] + dt * X[4] + hd2 * X[5] + g0 * fm1;
            float x4 = X[4] + dt * X[5] + g1 * fm1;
            float x5 = X[5] + g2 * fm1;
            X[0] = x0; X[1] = x1; X[2] = x2; X[3] = x3; X[4] = x4; X[5] = x5;
            float Gs[6] = {gt0 * fm2, gt1 * fm2, gt2 * fm2, gt3 * fm3, gt4 * fm3, gt5 * fm3};
#pragma unroll
            for (int ccx = 0; ccx < 6; ccx++) {
                P[0][ccx] += dt * P[1][ccx] + hd2 * P[2][ccx];
                P[1][ccx] += dt * P[2][ccx];
                P[3][ccx] += dt * P[4][ccx] + hd2 * P[5][ccx];
                P[4][ccx] += dt * P[5][ccx];
            }
#pragma unroll
            for (int rr = 0; rr < 6; rr++) {
                P[rr][0] += dt * P[rr][1] + hd2 * P[rr][2];
                P[rr][1] += dt * P[rr][2];
                P[rr][3] += dt * P[rr][4] + hd2 * P[rr][5];
                P[rr][4] += dt * P[rr][5];
            }
#pragma unroll
            for (int i = 0; i < 6; i++)
#pragma unroll
                for (int j = 0; j < 6; j++) P[i][j] += Gs[i] * Gs[j];

            if (valid && jh == 0) {
                float sx = sqrtf(P[0][0]);
                float sy = sqrtf(P[3][3]);
                float rho = __fdividef(P[0][3] + P[3][0], 2.0f * sx * sy);
                size_t o = ((size_t)t * B + e) * 5;
                out[o + 0] = X[0];
                out[o + 1] = X[3];
                out[o + 2] = sx;
                out[o + 3] = sy;
                out[o + 4] = rho;
            }
        }
    }
}

extern "C" void kernel_launch(void* const* d_in, const int* in_sizes, int n_in,
                              void* d_out, int out_size) {
    const float* hist  = (const float*)d_in[0];
    const float* psx   = (const float*)d_in[1];
    const float* psy   = (const float*)d_in[2];
    const float* vsx   = (const float*)d_in[3];
    const float* vsy   = (const float*)d_in[4];
    const float* asx   = (const float*)d_in[5];
    const float* asy   = (const float*)d_in[6];
    const float* jerk  = (const float*)d_in[7];
    const float* coefG = (const float*)d_in[8];
    const float* GR    = (const float*)d_in[9];
    const float* cfW   = (const float*)d_in[10];
    const float* cfb   = (const float*)d_in[11];
    const float* Wih   = (const float*)d_in[12];
    const float* Whh   = (const float*)d_in[13];
    const float* bih   = (const float*)d_in[14];
    const float* bhh   = (const float*)d_in[15];
    const float* coW   = (const float*)d_in[16];
    const float* cob   = (const float*)d_in[17];
    float* out = (float*)d_out;

    const int T = 16;
    int B  = in_sizes[0] / (2 * T);
    int LP = out_size / (B * 5);

    size_t smem = (size_t)SMEM_FLOATS * sizeof(float);  // 162368 bytes
    cudaFuncSetAttribute(kalman_lstm_kernel,
                         cudaFuncAttributeMaxDynamicSharedMemorySize, (int)smem);

    int grid = (B + EL - 1) / EL;
    kalman_lstm_kernel<<<grid, TB, smem>>>(
        hist, psx, psy, vsx, vsy, asx, asy, jerk, coefG, GR,
        cfW, cfb, Wih, Whh, bih, bhh, coW, cob, out, B, LP);
}

// round 15
// speedup vs baseline: 2.3084x; 1.1347x over previous
#include <cuda_runtime.h>
#include <cstdint>

#define TB  256
#define EL  128       // elements per CTA
#define SA  68        // act/weight tile row stride (floats)
#define GS  17        // per-warp gbuf col stride

// ---- smem float offsets ----
#define OFF_BIAS 0                      // float4[32]
#define OFF_CF   128                    // float[32*8]
#define OFF_CO   384                    // float4[32]
#define OFF_COB  512                    // float[4] (+pad)
#define OFF_AB   528
#define OFF_AS   (OFF_AB + 128*SA)
#define OFF_BB   (OFF_AS + 128*SA)
#define OFF_BS   (OFF_BB + 128*SA)
#define OFF_G    (OFF_BS + 128*SA)      // 8 warps x [32 col][GS]
#define SMEM_FLOATS (OFF_G + 8*32*GS)   // 39696 floats = 158784 B

extern __shared__ float s_raw[];

__device__ __forceinline__ float fsig(float x) { float e = __expf(-x); return __fdividef(1.f, 1.f + e); }
__device__ __forceinline__ float ftanh(float x) { float e = __expf(2.f * x); return 1.f - __fdividef(2.f, e + 1.f); }
__device__ __forceinline__ uint32_t tf32b(float f) {
    uint32_t u; asm("cvt.rna.tf32.f32 %0, %1;" : "=r"(u) : "f"(f)); return u;
}
__device__ __forceinline__ void mma8(float* d, const uint32_t* a, uint32_t b0, uint32_t b1) {
    asm volatile(
        "mma.sync.aligned.m16n8k8.row.col.f32.tf32.tf32.f32 "
        "{%0,%1,%2,%3}, {%4,%5,%6,%7}, {%8,%9}, {%0,%1,%2,%3};"
        : "+f"(d[0]), "+f"(d[1]), "+f"(d[2]), "+f"(d[3])
        : "r"(a[0]), "r"(a[1]), "r"(a[2]), "r"(a[3]), "r"(b0), "r"(b1));
}

__global__ void __launch_bounds__(TB, 1) kalman_lstm_kernel(
    const float* __restrict__ hist,
    const float* __restrict__ p_psx, const float* __restrict__ p_psy,
    const float* __restrict__ p_vsx, const float* __restrict__ p_vsy,
    const float* __restrict__ p_asx, const float* __restrict__ p_asy,
    const float* __restrict__ p_jerk, const float* __restrict__ p_coefG,
    const float* __restrict__ p_GR,
    const float* __restrict__ cfW, const float* __restrict__ cfb,
    const float* __restrict__ Wih, const float* __restrict__ Whh,
    const float* __restrict__ bih, const float* __restrict__ bhh,
    const float* __restrict__ coW, const float* __restrict__ cob,
    float* __restrict__ out,
    int B, int LP)
{
    const int tid = threadIdx.x;
    const int w = tid >> 5;
    const int lane = tid & 31;
    const int gr = lane >> 2, tq = lane & 3;
    const int rb = w * 16;             // my m-tile rows == my elements
    const int erow = lane >> 1;        // element row within tile (0..15)
    const int el = rb + erow;          // my element (CTA-local)
    const int half = lane & 1;         // j-half
    uint32_t* s_u32 = reinterpret_cast<uint32_t*>(s_raw);

    // ---- small tables ----
    if (tid < 32) {
        int j = tid;
        reinterpret_cast<float4*>(s_raw + OFF_BIAS)[j] = make_float4(
            bih[j] + bhh[j],           bih[32 + j] + bhh[32 + j],
            bih[64 + j] + bhh[64 + j], bih[96 + j] + bhh[96 + j]);
        reinterpret_cast<float4*>(s_raw + OFF_CO)[j] = make_float4(
            coW[j], coW[32 + j], coW[64 + j], coW[96 + j]);
#pragma unroll
        for (int k = 0; k < 6; k++) s_raw[OFF_CF + j * 8 + k] = cfW[j * 6 + k];
        s_raw[OFF_CF + j * 8 + 6] = cfb[j];
        s_raw[OFF_CF + j * 8 + 7] = 0.0f;
    }
    if (tid == 32) {
        s_raw[OFF_COB + 0] = cob[0]; s_raw[OFF_COB + 1] = cob[1];
        s_raw[OFF_COB + 2] = cob[2]; s_raw[OFF_COB + 3] = cob[3];
    }

    // ---- weight tiles: row n = 32*chunk + 4*q + gate ; j = 8*chunk + q ----
    {
        int n = tid & 127;
        int gate = n & 3, q = (n >> 2) & 7, ch = n >> 5;
        int j = ch * 8 + q;
        const float* wi = Wih + (gate * 32 + j) * 32;
        const float* wh = Whh + (gate * 32 + j) * 32;
        int k0 = (tid >> 7) * 32;
#pragma unroll 4
        for (int kk = 0; kk < 32; kk++) {
            int k = k0 + kk;
            float wv = (k < 32) ? wi[k] : wh[k - 32];
            uint32_t bg = tf32b(wv);
            float resid = wv - __uint_as_float(bg);
            s_u32[OFF_BB + n * SA + k] = bg;
            s_u32[OFF_BS + n * SA + k] = tf32b(resid);
        }
    }
    // zero act tiles
    for (int i = tid; i < 2 * 128 * SA; i += TB) s_raw[OFF_AB + i] = 0.0f;
    __syncthreads();   // ONLY CTA barrier (weights/tables/act-zero published)

    // ---- per-thread Kalman (duplicated across the 2 halves of an element) ----
    const float dt = 0.2f, hd2 = 0.02f;
    const float g0 = (float)(0.2 * 0.2 * 0.2 / 6.0), g1 = 0.02f, g2 = 0.2f;
    const int e_raw = blockIdx.x * EL + el;
    const bool valid = e_raw < B;
    const int e = valid ? e_raw : (B - 1);
    const float2* hist2 = reinterpret_cast<const float2*>(hist);

    float tg[6];
#pragma unroll
    for (int i = 0; i < 6; i++) tg[i] = tanhf(p_coefG[i]);
    const float jk0 = p_jerk[0], jk1 = p_jerk[1];
    const float Ghx0 = g0 * tg[0] * jk0, Ghx1 = g1 * tg[1] * jk0, Ghx2 = g2 * tg[2] * jk0;
    const float Ghy0 = g0 * tg[3] * jk1, Ghy1 = g1 * tg[4] * jk1, Ghy2 = g2 * tg[5] * jk1;
    const float gt0 = g0 * tg[0], gt1 = g1 * tg[1], gt2 = g2 * tg[2];
    const float gt3 = g0 * tg[3], gt4 = g1 * tg[4], gt5 = g2 * tg[5];
    const float gr0_ = p_GR[0], gr1_ = p_GR[1];
    const float R00 = gr0_ * gr0_, R01 = gr0_ * gr1_, R11 = gr1_ * gr1_;

    float2 z0 = hist2[e];
    float2 z1 = hist2[(size_t)B + e];
    float X[6];
    X[0] = z0.x; X[1] = (z1.x - z0.x) / dt; X[2] = 0.0f;
    X[3] = (z1.y - z0.y) / dt; X[4] = 0.0f; X[5] = 0.0f;
    float P[6][6];
#pragma unroll
    for (int i = 0; i < 6; i++)
#pragma unroll
        for (int j = 0; j < 6; j++) P[i][j] = 0.0f;
    {
        float d0 = p_psx[0], d1 = p_vsx[0], d2 = p_asx[0];
        float d3 = p_psy[0], d4 = p_vsy[0], d5 = p_asy[0];
        P[0][0] = d0 * d0; P[1][1] = d1 * d1; P[2][2] = d2 * d2;
        P[3][3] = d3 * d3; P[4][4] = d4 * d4; P[5][5] = d5 * d5;
    }
    float creg[4][4];
#pragma unroll
    for (int c = 0; c < 4; c++)
#pragma unroll
        for (int q = 0; q < 4; q++) creg[c][q] = 0.0f;

    float* G = s_raw + OFF_G + w * 32 * GS;   // my warp's gate staging
    const int TS = 15 + LP;

#pragma unroll 1
    for (int step = 0; step < TS; step++) {
        // ---- feat: my element's m rows (m = half*16 .. +15) -> A tiles ----
        {
            const float4* cf = reinterpret_cast<const float4*>(s_raw + OFF_CF);
#pragma unroll
            for (int m0 = 0; m0 < 16; m0 += 4) {
                uint4 vb, vs;
                uint32_t* pb = &vb.x; uint32_t* ps = &vs.x;
#pragma unroll
                for (int qq = 0; qq < 4; qq++) {
                    int m = half * 16 + m0 + qq;
                    float4 a = cf[m * 2];
                    float4 b = cf[m * 2 + 1];
                    float acc = b.z;
                    acc = fmaf(a.x, X[0], acc);
                    acc = fmaf(a.y, X[1], acc);
                    acc = fmaf(a.z, X[2], acc);
                    acc = fmaf(a.w, X[3], acc);
                    acc = fmaf(b.x, X[4], acc);
                    acc = fmaf(b.y, X[5], acc);
                    float f = ftanh(acc);
                    uint32_t bg = tf32b(f);
                    pb[qq] = bg;
                    ps[qq] = tf32b(f - __uint_as_float(bg));
                }
                int k = half * 16 + m0;
                *reinterpret_cast<uint4*>(s_u32 + OFF_AB + el * SA + k) = vb;
                *reinterpret_cast<uint4*>(s_u32 + OFF_AS + el * SA + k) = vs;
            }
        }
        __syncwarp();   // feat (+ prev-step h) visible to my warp's fragment loads

        // ---- big-A fragments for my m-tile ----
        uint32_t ab[8][4];
#pragma unroll
        for (int kt = 0; kt < 8; kt++) {
            int r = OFF_AB + (rb + gr) * SA + kt * 8 + tq;
            ab[kt][0] = s_u32[r];
            ab[kt][1] = s_u32[r + 8 * SA];
            ab[kt][2] = s_u32[r + 4];
            ab[kt][3] = s_u32[r + 8 * SA + 4];
        }

        float cm0 = 0.f, cm1 = 0.f, cm2 = 0.f, cm3 = 0.f;
        uint32_t hbq[4][4], hsq[4][4];

#pragma unroll
        for (int chunk = 0; chunk < 4; chunk++) {
            float d[4][4];
#pragma unroll
            for (int nt = 0; nt < 4; nt++)
#pragma unroll
                for (int k4 = 0; k4 < 4; k4++) d[nt][k4] = 0.0f;

            const int bbase = (chunk * 32 + gr) * SA + tq;
#pragma unroll
            for (int kt = 0; kt < 8; kt++) {
                uint32_t as[4];
                {
                    int r = OFF_AS + (rb + gr) * SA + kt * 8 + tq;
                    as[0] = s_u32[r];       as[1] = s_u32[r + 8 * SA];
                    as[2] = s_u32[r + 4];   as[3] = s_u32[r + 8 * SA + 4];
                }
#pragma unroll
                for (int nt = 0; nt < 4; nt++) {
                    int bi = bbase + nt * 8 * SA + kt * 8;
                    uint32_t bb0 = s_u32[OFF_BB + bi];
                    uint32_t bb1 = s_u32[OFF_BB + bi + 4];
                    uint32_t bs0 = s_u32[OFF_BS + bi];
                    uint32_t bs1 = s_u32[OFF_BS + bi + 4];
                    mma8(d[nt], ab[kt], bb0, bb1);
                    mma8(d[nt], as,     bb0, bb1);
                    mma8(d[nt], ab[kt], bs0, bs1);
                }
            }

            __syncwarp();   // prior epilogue reads of G done
            // ---- store D into my warp's G: G[col][row], col 0..31, row 0..15 ----
#pragma unroll
            for (int nt = 0; nt < 4; nt++) {
                int c0 = nt * 8 + 2 * tq, c1 = c0 + 1;
                G[c0 * GS + gr]     = d[nt][0];
                G[c1 * GS + gr]     = d[nt][1];
                G[c0 * GS + gr + 8] = d[nt][2];
                G[c1 * GS + gr + 8] = d[nt][3];
            }
            __syncwarp();   // G complete

            // ---- epilogue: my 4 j's of this chunk for my element ----
            const float4* bias4 = reinterpret_cast<const float4*>(s_raw + OFF_BIAS);
            const float4* co4   = reinterpret_cast<const float4*>(s_raw + OFF_CO);
#pragma unroll
            for (int q = 0; q < 4; q++) {
                int jn = half * 4 + q;         // j within chunk (0..7)
                int j  = chunk * 8 + jn;       // global j
                float gi = G[(4 * jn + 0) * GS + erow];
                float gf = G[(4 * jn + 1) * GS + erow];
                float gg = G[(4 * jn + 2) * GS + erow];
                float go = G[(4 * jn + 3) * GS + erow];
                float4 bq = bias4[j];
                gi += bq.x; gf += bq.y; gg += bq.z; go += bq.w;
                float cold = creg[chunk][q];
                float cj = fmaf(fsig(gf), cold, fsig(gi) * ftanh(gg));
                creg[chunk][q] = cj;
                float h = fsig(go) * ftanh(cj);
                uint32_t bg = tf32b(h);
                hbq[chunk][q] = bg;
                hsq[chunk][q] = tf32b(h - __uint_as_float(bg));
                float4 cwt = co4[j];
                cm0 = fmaf(cwt.x, h, cm0);
                cm1 = fmaf(cwt.y, h, cm1);
                cm2 = fmaf(cwt.z, h, cm2);
                cm3 = fmaf(cwt.w, h, cm3);
            }
        }

        // ---- write h(t) to A tiles (deferred: all chunks consumed h(t-1)) ----
#pragma unroll
        for (int c = 0; c < 4; c++) {
            int k = 32 + c * 8 + half * 4;
            *reinterpret_cast<uint4*>(s_u32 + OFF_AB + el * SA + k) =
                make_uint4(hbq[c][0], hbq[c][1], hbq[c][2], hbq[c][3]);
            *reinterpret_cast<uint4*>(s_u32 + OFF_AS + el * SA + k) =
                make_uint4(hsq[c][0], hsq[c][1], hsq[c][2], hsq[c][3]);
        }

        // ================= Kalman (per-thread fp32, duplicated per half) ====
        if (step < 15) {
            int t = step + 1;
            float x0 = X[0] + dt * X[1] + hd2 * X[2];
            float x1 = X[1] + dt * X[2];
            float x3 = X[3] + dt * X[4] + hd2 * X[5];
            float x4 = X[4] + dt * X[5];
            X[0] = x0; X[1] = x1; X[3] = x3; X[4] = x4;
#pragma unroll
            for (int ccx = 0; ccx < 6; ccx++) {
                P[0][ccx] += dt * P[1][ccx] + hd2 * P[2][ccx];
                P[1][ccx] += dt * P[2][ccx];
                P[3][ccx] += dt * P[4][ccx] + hd2 * P[5][ccx];
                P[4][ccx] += dt * P[5][ccx];
            }
#pragma unroll
            for (int rr = 0; rr < 6; rr++) {
                P[rr][0] += dt * P[rr][1] + hd2 * P[rr][2];
                P[rr][1] += dt * P[rr][2];
                P[rr][3] += dt * P[rr][4] + hd2 * P[rr][5];
                P[rr][4] += dt * P[rr][5];
            }
            {
                float gx[3] = {Ghx0, Ghx1, Ghx2}, gy[3] = {Ghy0, Ghy1, Ghy2};
#pragma unroll
                for (int a = 0; a < 3; a++)
#pragma unroll
                    for (int bb = 0; bb < 3; bb++) {
                        P[a][bb]         += gx[a] * gx[bb];
                        P[3 + a][3 + bb] += gy[a] * gy[bb];
                    }
            }
            float2 z = hist2[(size_t)t * B + e];
            float yx = z.x - X[0], yy = z.y - X[3];
            float S00 = P[0][0] + R00, S01 = P[0][3] + R01;
            float S10 = P[3][0] + R01, S11 = P[3][3] + R11;
            float rdet = 1.0f / (S00 * S11 - S01 * S10);
            float si00 =  S11 * rdet, si01 = -S01 * rdet;
            float si10 = -S10 * rdet, si11 =  S00 * rdet;
            float K0[6], K1[6];
#pragma unroll
            for (int i = 0; i < 6; i++) {
                K0[i] = P[i][0] * si00 + P[i][3] * si10;
                K1[i] = P[i][0] * si01 + P[i][3] * si11;
            }
#pragma unroll
            for (int i = 0; i < 6; i++) X[i] += K0[i] * yx + K1[i] * yy;
            float r0[6], r3[6];
#pragma unroll
            for (int j = 0; j < 6; j++) { r0[j] = P[0][j]; r3[j] = P[3][j]; }
#pragma unroll
            for (int i = 0; i < 6; i++)
#pragma unroll
                for (int j = 0; j < 6; j++) P[i][j] -= K0[i] * r0[j] + K1[i] * r3[j];
        } else {
            int t = step - 15;
            // combine command partials across the 2 j-halves (lanes 2k / 2k+1)
            cm0 += __shfl_xor_sync(0xffffffffu, cm0, 1);
            cm1 += __shfl_xor_sync(0xffffffffu, cm1, 1);
            cm2 += __shfl_xor_sync(0xffffffffu, cm2, 1);
            cm3 += __shfl_xor_sync(0xffffffffu, cm3, 1);
            float fm0 = cm0 + s_raw[OFF_COB + 0];
            float fm1 = cm1 + s_raw[OFF_COB + 1];
            float fm2 = cm2 + s_raw[OFF_COB + 2];
            float fm3 = cm3 + s_raw[OFF_COB + 3];

            float x0 = X[0] + dt * X[1] + hd2 * X[2] + g0 * fm0;
            float x1 = X[1] + dt * X[2] + g1 * fm0;
            float x2 = X[2] + g2 * fm0;
            float x3 = X[3] + dt * X[4] + hd2 * X[5] + g0 * fm1;
            float x4 = X[4] + dt * X[5] + g1 * fm1;
            float x5 = X[5] + g2 * fm1;
            X[0] = x0; X[1] = x1; X[2] = x2; X[3] = x3; X[4] = x4; X[5] = x5;
            float Gs[6] = {gt0 * fm2, gt1 * fm2, gt2 * fm2, gt3 * fm3, gt4 * fm3, gt5 * fm3};
#pragma unroll
            for (int ccx = 0; ccx < 6; ccx++) {
                P[0][ccx] += dt * P[1][ccx] + hd2 * P[2][ccx];
                P[1][ccx] += dt * P[2][ccx];
                P[3][ccx] += dt * P[4][ccx] + hd2 * P[5][ccx];
                P[4][ccx] += dt * P[5][ccx];
            }
#pragma unroll
            for (int rr = 0; rr < 6; rr++) {
                P[rr][0] += dt * P[rr][1] + hd2 * P[rr][2];
                P[rr][1] += dt * P[rr][2];
                P[rr][3] += dt * P[rr][4] + hd2 * P[rr][5];
                P[rr][4] += dt * P[rr][5];
            }
#pragma unroll
            for (int i = 0; i < 6; i++)
#pragma unroll
                for (int j = 0; j < 6; j++) P[i][j] += Gs[i] * Gs[j];

            if (valid && half == 0) {
                float sx = sqrtf(P[0][0]);
                float sy = sqrtf(P[3][3]);
                float rho = __fdividef(P[0][3] + P[3][0], 2.0f * sx * sy);
                size_t o = ((size_t)t * B + e) * 5;
                out[o + 0] = X[0];
                out[o + 1] = X[3];
                out[o + 2] = sx;
                out[o + 3] = sy;
                out[o + 4] = rho;
            }
        }
    }
}

extern "C" void kernel_launch(void* const* d_in, const int* in_sizes, int n_in,
                              void* d_out, int out_size) {
    const float* hist  = (const float*)d_in[0];
    const float* psx   = (const float*)d_in[1];
    const float* psy   = (const float*)d_in[2];
    const float* vsx   = (const float*)d_in[3];
    const float* vsy   = (const float*)d_in[4];
    const float* asx   = (const float*)d_in[5];
    const float* asy   = (const float*)d_in[6];
    const float* jerk  = (const float*)d_in[7];
    const float* coefG = (const float*)d_in[8];
    const float* GR    = (const float*)d_in[9];
    const float* cfW   = (const float*)d_in[10];
    const float* cfb   = (const float*)d_in[11];
    const float* Wih   = (const float*)d_in[12];
    const float* Whh   = (const float*)d_in[13];
    const float* bih   = (const float*)d_in[14];
    const float* bhh   = (const float*)d_in[15];
    const float* coW   = (const float*)d_in[16];
    const float* cob   = (const float*)d_in[17];
    float* out = (float*)d_out;

    const int T = 16;
    int B  = in_sizes[0] / (2 * T);
    int LP = out_size / (B * 5);

    size_t smem = (size_t)SMEM_FLOATS * sizeof(float);  // 158784 bytes
    cudaFuncSetAttribute(kalman_lstm_kernel,
                         cudaFuncAttributeMaxDynamicSharedMemorySize, (int)smem);

    int grid = (B + EL - 1) / EL;
    kalman_lstm_kernel<<<grid, TB, smem>>>(
        hist, psx, psy, vsx, vsy, asx, asy, jerk, coefG, GR,
        cfW, cfb, Wih, Whh, bih, bhh, coW, cob, out, B, LP);
}

// round 16
// speedup vs baseline: 2.3855x; 1.0334x over previous
#include <cuda_runtime.h>
#include <cstdint>

#define TB  256
#define EL  128       // elements per CTA
#define SA  68        // act tile row stride (floats)
#define GS  17        // per-warp gbuf col stride

// ---- smem float offsets ----
#define OFF_BIAS 0                      // float4[32]
#define OFF_CF   128                    // float[32*8]
#define OFF_CO   384                    // float4[32]
#define OFF_COB  512                    // float[4] (+pad to 528)
#define OFF_AB   528                    // act big   [128][SA]
#define OFF_AS   (OFF_AB + 128*SA)      // act small
#define OFF_B4   (OFF_AS + 128*SA)      // packed W: uint4[8 kt][128 n * 4 tq]
#define OFF_G    (OFF_B4 + 16384)       // 8 warps x [32 col][GS]
#define SMEM_FLOATS (OFF_G + 8*32*GS)   // 38672 floats = 154688 B

extern __shared__ float s_raw[];

__device__ __forceinline__ float fsig(float x) { float e = __expf(-x); return __fdividef(1.f, 1.f + e); }
__device__ __forceinline__ float ftanh(float x) { float e = __expf(2.f * x); return 1.f - __fdividef(2.f, e + 1.f); }
__device__ __forceinline__ uint32_t tf32b(float f) {
    uint32_t u; asm("cvt.rna.tf32.f32 %0, %1;" : "=r"(u) : "f"(f)); return u;
}
__device__ __forceinline__ void mma8(float* d, const uint32_t* a, uint32_t b0, uint32_t b1) {
    asm volatile(
        "mma.sync.aligned.m16n8k8.row.col.f32.tf32.tf32.f32 "
        "{%0,%1,%2,%3}, {%4,%5,%6,%7}, {%8,%9}, {%0,%1,%2,%3};"
        : "+f"(d[0]), "+f"(d[1]), "+f"(d[2]), "+f"(d[3])
        : "r"(a[0]), "r"(a[1]), "r"(a[2]), "r"(a[3]), "r"(b0), "r"(b1));
}

__global__ void __launch_bounds__(TB, 1) kalman_lstm_kernel(
    const float* __restrict__ hist,
    const float* __restrict__ p_psx, const float* __restrict__ p_psy,
    const float* __restrict__ p_vsx, const float* __restrict__ p_vsy,
    const float* __restrict__ p_asx, const float* __restrict__ p_asy,
    const float* __restrict__ p_jerk, const float* __restrict__ p_coefG,
    const float* __restrict__ p_GR,
    const float* __restrict__ cfW, const float* __restrict__ cfb,
    const float* __restrict__ Wih, const float* __restrict__ Whh,
    const float* __restrict__ bih, const float* __restrict__ bhh,
    const float* __restrict__ coW, const float* __restrict__ cob,
    float* __restrict__ out,
    int B, int LP)
{
    const int tid = threadIdx.x;
    const int w = tid >> 5;
    const int lane = tid & 31;
    const int gr = lane >> 2, tq = lane & 3;
    const int rb = w * 16;             // my m-tile rows == my elements
    const int erow = lane >> 1;        // element row within tile (0..15)
    const int el = rb + erow;          // my element (CTA-local)
    const int half = lane & 1;         // j-half
    uint32_t* s_u32 = reinterpret_cast<uint32_t*>(s_raw);

    // ---- small tables ----
    if (tid < 32) {
        int j = tid;
        reinterpret_cast<float4*>(s_raw + OFF_BIAS)[j] = make_float4(
            bih[j] + bhh[j],           bih[32 + j] + bhh[32 + j],
            bih[64 + j] + bhh[64 + j], bih[96 + j] + bhh[96 + j]);
        reinterpret_cast<float4*>(s_raw + OFF_CO)[j] = make_float4(
            coW[j], coW[32 + j], coW[64 + j], coW[96 + j]);
#pragma unroll
        for (int k = 0; k < 6; k++) s_raw[OFF_CF + j * 8 + k] = cfW[j * 6 + k];
        s_raw[OFF_CF + j * 8 + 6] = cfb[j];
        s_raw[OFF_CF + j * 8 + 7] = 0.0f;
    }
    if (tid == 32) {
        s_raw[OFF_COB + 0] = cob[0]; s_raw[OFF_COB + 1] = cob[1];
        s_raw[OFF_COB + 2] = cob[2]; s_raw[OFF_COB + 3] = cob[3];
    }

    // ---- packed weight tile: uint4 {bb(k), bb(k+4), bs(k), bs(k+4)} ----
    // row n = 32*chunk + 4*q + gate ; j = 8*chunk + q ; k = kt*8 + tq
    {
        int n = tid & 127;
        int gate = n & 3, q = (n >> 2) & 7, ch = n >> 5;
        int j = ch * 8 + q;
        const float* wi = Wih + (gate * 32 + j) * 32;
        const float* wh = Whh + (gate * 32 + j) * 32;
        int kt0 = (tid >> 7) * 4;
#pragma unroll
        for (int kk = 0; kk < 4; kk++) {
            int kt = kt0 + kk;
#pragma unroll
            for (int t4 = 0; t4 < 4; t4++) {
                int k0 = kt * 8 + t4, k1 = k0 + 4;
                float w0 = (k0 < 32) ? wi[k0] : wh[k0 - 32];
                float w1 = (k1 < 32) ? wi[k1] : wh[k1 - 32];
                uint32_t b0 = tf32b(w0), b1 = tf32b(w1);
                uint32_t s0 = tf32b(w0 - __uint_as_float(b0));
                uint32_t s1 = tf32b(w1 - __uint_as_float(b1));
                reinterpret_cast<uint4*>(s_u32 + OFF_B4)[kt * 512 + n * 4 + t4] =
                    make_uint4(b0, b1, s0, s1);
            }
        }
    }
    // zero act tiles
    for (int i = tid; i < 2 * 128 * SA; i += TB) s_raw[OFF_AB + i] = 0.0f;
    __syncthreads();   // ONLY CTA barrier

    // ---- per-thread Kalman (duplicated across the 2 halves of an element) ----
    const float dt = 0.2f, hd2 = 0.02f;
    const float g0 = (float)(0.2 * 0.2 * 0.2 / 6.0), g1 = 0.02f, g2 = 0.2f;
    const int e_raw = blockIdx.x * EL + el;
    const bool valid = e_raw < B;
    const int e = valid ? e_raw : (B - 1);
    const float2* hist2 = reinterpret_cast<const float2*>(hist);

    float tg[6];
#pragma unroll
    for (int i = 0; i < 6; i++) tg[i] = tanhf(p_coefG[i]);
    const float jk0 = p_jerk[0], jk1 = p_jerk[1];
    const float Ghx0 = g0 * tg[0] * jk0, Ghx1 = g1 * tg[1] * jk0, Ghx2 = g2 * tg[2] * jk0;
    const float Ghy0 = g0 * tg[3] * jk1, Ghy1 = g1 * tg[4] * jk1, Ghy2 = g2 * tg[5] * jk1;
    const float gt0 = g0 * tg[0], gt1 = g1 * tg[1], gt2 = g2 * tg[2];
    const float gt3 = g0 * tg[3], gt4 = g1 * tg[4], gt5 = g2 * tg[5];
    const float gr0_ = p_GR[0], gr1_ = p_GR[1];
    const float R00 = gr0_ * gr0_, R01 = gr0_ * gr1_, R11 = gr1_ * gr1_;

    float2 z0 = hist2[e];
    float2 z1 = hist2[(size_t)B + e];
    float X[6];
    X[0] = z0.x; X[1] = (z1.x - z0.x) / dt; X[2] = 0.0f;
    X[3] = (z1.y - z0.y) / dt; X[4] = 0.0f; X[5] = 0.0f;
    float P[6][6];
#pragma unroll
    for (int i = 0; i < 6; i++)
#pragma unroll
        for (int j = 0; j < 6; j++) P[i][j] = 0.0f;
    {
        float d0 = p_psx[0], d1 = p_vsx[0], d2 = p_asx[0];
        float d3 = p_psy[0], d4 = p_vsy[0], d5 = p_asy[0];
        P[0][0] = d0 * d0; P[1][1] = d1 * d1; P[2][2] = d2 * d2;
        P[3][3] = d3 * d3; P[4][4] = d4 * d4; P[5][5] = d5 * d5;
    }
    float creg[4][4];
#pragma unroll
    for (int c = 0; c < 4; c++)
#pragma unroll
        for (int q = 0; q < 4; q++) creg[c][q] = 0.0f;

    float* G = s_raw + OFF_G + w * 32 * GS;   // my warp's gate staging
    const uint4* B4 = reinterpret_cast<const uint4*>(s_u32 + OFF_B4);
    const int TS = 15 + LP;

#pragma unroll 1
    for (int step = 0; step < TS; step++) {
        // ---- feat: my element's m rows (m = half*16 .. +15) -> A tiles ----
        {
            const float4* cf = reinterpret_cast<const float4*>(s_raw + OFF_CF);
#pragma unroll
            for (int m0 = 0; m0 < 16; m0 += 4) {
                uint4 vb, vs;
                uint32_t* pb = &vb.x; uint32_t* ps = &vs.x;
#pragma unroll
                for (int qq = 0; qq < 4; qq++) {
                    int m = half * 16 + m0 + qq;
                    float4 a = cf[m * 2];
                    float4 b = cf[m * 2 + 1];
                    float acc = b.z;
                    acc = fmaf(a.x, X[0], acc);
                    acc = fmaf(a.y, X[1], acc);
                    acc = fmaf(a.z, X[2], acc);
                    acc = fmaf(a.w, X[3], acc);
                    acc = fmaf(b.x, X[4], acc);
                    acc = fmaf(b.y, X[5], acc);
                    float f = ftanh(acc);
                    uint32_t bg = tf32b(f);
                    pb[qq] = bg;
                    ps[qq] = tf32b(f - __uint_as_float(bg));
                }
                int k = half * 16 + m0;
                *reinterpret_cast<uint4*>(s_u32 + OFF_AB + el * SA + k) = vb;
                *reinterpret_cast<uint4*>(s_u32 + OFF_AS + el * SA + k) = vs;
            }
        }
        __syncwarp();   // feat (+ prev-step h) visible to my warp's fragment loads

        // ---- A fragments for my m-tile: big AND small, all k, hoisted ----
        uint32_t ab[8][4], asf[8][4];
#pragma unroll
        for (int kt = 0; kt < 8; kt++) {
            int r = OFF_AB + (rb + gr) * SA + kt * 8 + tq;
            ab[kt][0] = s_u32[r];
            ab[kt][1] = s_u32[r + 8 * SA];
            ab[kt][2] = s_u32[r + 4];
            ab[kt][3] = s_u32[r + 8 * SA + 4];
            int rs = r + (OFF_AS - OFF_AB);
            asf[kt][0] = s_u32[rs];
            asf[kt][1] = s_u32[rs + 8 * SA];
            asf[kt][2] = s_u32[rs + 4];
            asf[kt][3] = s_u32[rs + 8 * SA + 4];
        }
        __syncwarp();   // all fragment loads done before chunk-0 h writes

        float cm0 = 0.f, cm1 = 0.f, cm2 = 0.f, cm3 = 0.f;

#pragma unroll
        for (int chunk = 0; chunk < 4; chunk++) {
            float d[4][4];
#pragma unroll
            for (int nt = 0; nt < 4; nt++)
#pragma unroll
                for (int k4 = 0; k4 < 4; k4++) d[nt][k4] = 0.0f;

#pragma unroll
            for (int kt = 0; kt < 8; kt++) {
#pragma unroll
                for (int nt = 0; nt < 4; nt++) {
                    uint4 bw = B4[kt * 512 + (chunk * 32 + nt * 8 + gr) * 4 + tq];
                    mma8(d[nt], ab[kt],  bw.x, bw.y);
                    mma8(d[nt], asf[kt], bw.x, bw.y);
                    mma8(d[nt], ab[kt],  bw.z, bw.w);
                }
            }

            __syncwarp();   // prior epilogue reads of G done
#pragma unroll
            for (int nt = 0; nt < 4; nt++) {
                int c0 = nt * 8 + 2 * tq, c1 = c0 + 1;
                G[c0 * GS + gr]     = d[nt][0];
                G[c1 * GS + gr]     = d[nt][1];
                G[c0 * GS + gr + 8] = d[nt][2];
                G[c1 * GS + gr + 8] = d[nt][3];
            }
            __syncwarp();   // G complete

            // ---- epilogue: my 4 j's of this chunk; h written immediately ----
            const float4* bias4 = reinterpret_cast<const float4*>(s_raw + OFF_BIAS);
            const float4* co4   = reinterpret_cast<const float4*>(s_raw + OFF_CO);
            uint32_t hb[4], hs[4];
#pragma unroll
            for (int q = 0; q < 4; q++) {
                int jn = half * 4 + q;         // j within chunk (0..7)
                int j  = chunk * 8 + jn;       // global j
                float gi = G[(4 * jn + 0) * GS + erow];
                float gf = G[(4 * jn + 1) * GS + erow];
                float gg = G[(4 * jn + 2) * GS + erow];
                float go = G[(4 * jn + 3) * GS + erow];
                float4 bq = bias4[j];
                gi += bq.x; gf += bq.y; gg += bq.z; go += bq.w;
                float cold = creg[chunk][q];
                float cj = fmaf(fsig(gf), cold, fsig(gi) * ftanh(gg));
                creg[chunk][q] = cj;
                float h = fsig(go) * ftanh(cj);
                uint32_t bg = tf32b(h);
                hb[q] = bg;
                hs[q] = tf32b(h - __uint_as_float(bg));
                float4 cwt = co4[j];
                cm0 = fmaf(cwt.x, h, cm0);
                cm1 = fmaf(cwt.y, h, cm1);
                cm2 = fmaf(cwt.z, h, cm2);
                cm3 = fmaf(cwt.w, h, cm3);
            }
            {
                int k = 32 + chunk * 8 + half * 4;
                *reinterpret_cast<uint4*>(s_u32 + OFF_AB + el * SA + k) =
                    make_uint4(hb[0], hb[1], hb[2], hb[3]);
                *reinterpret_cast<uint4*>(s_u32 + OFF_AS + el * SA + k) =
                    make_uint4(hs[0], hs[1], hs[2], hs[3]);
            }
        }

        // ================= Kalman (per-thread fp32, duplicated per half) ====
        if (step < 15) {
            int t = step + 1;
            float x0 = X[0] + dt * X[1] + hd2 * X[2];
            float x1 = X[1] + dt * X[2];
            float x3 = X[3] + dt * X[4] + hd2 * X[5];
            float x4 = X[4] + dt * X[5];
            X[0] = x0; X[1] = x1; X[3] = x3; X[4] = x4;
#pragma unroll
            for (int ccx = 0; ccx < 6; ccx++) {
                P[0][ccx] += dt * P[1][ccx] + hd2 * P[2][ccx];
                P[1][ccx] += dt * P[2][ccx];
                P[3][ccx] += dt * P[4][ccx] + hd2 * P[5][ccx];
                P[4][ccx] += dt * P[5][ccx];
            }
#pragma unroll
            for (int rr = 0; rr < 6; rr++) {
                P[rr][0] += dt * P[rr][1] + hd2 * P[rr][2];
                P[rr][1] += dt * P[rr][2];
                P[rr][3] += dt * P[rr][4] + hd2 * P[rr][5];
                P[rr][4] += dt * P[rr][5];
            }
            {
                float gx[3] = {Ghx0, Ghx1, Ghx2}, gy[3] = {Ghy0, Ghy1, Ghy2};
#pragma unroll
                for (int a = 0; a < 3; a++)
#pragma unroll
                    for (int bb = 0; bb < 3; bb++) {
                        P[a][bb]         += gx[a] * gx[bb];
                        P[3 + a][3 + bb] += gy[a] * gy[bb];
                    }
            }
            float2 z = hist2[(size_t)t * B + e];
            float yx = z.x - X[0], yy = z.y - X[3];
            float S00 = P[0][0] + R00, S01 = P[0][3] + R01;
            float S10 = P[3][0] + R01, S11 = P[3][3] + R11;
            float rdet = 1.0f / (S00 * S11 - S01 * S10);
            float si00 =  S11 * rdet, si01 = -S01 * rdet;
            float si10 = -S10 * rdet, si11 =  S00 * rdet;
            float K0[6], K1[6];
#pragma unroll
            for (int i = 0; i < 6; i++) {
                K0[i] = P[i][0] * si00 + P[i][3] * si10;
                K1[i] = P[i][0] * si01 + P[i][3] * si11;
            }
#pragma unroll
            for (int i = 0; i < 6; i++) X[i] += K0[i] * yx + K1[i] * yy;
            float r0[6], r3[6];
#pragma unroll
            for (int j = 0; j < 6; j++) { r0[j] = P[0][j]; r3[j] = P[3][j]; }
#pragma unroll
            for (int i = 0; i < 6; i++)
#pragma unroll
                for (int j = 0; j < 6; j++) P[i][j] -= K0[i] * r0[j] + K1[i] * r3[j];
        } else {
            int t = step - 15;
            // combine command partials across the 2 j-halves (lanes 2k / 2k+1)
            cm0 += __shfl_xor_sync(0xffffffffu, cm0, 1);
            cm1 += __shfl_xor_sync(0xffffffffu, cm1, 1);
            cm2 += __shfl_xor_sync(0xffffffffu, cm2, 1);
            cm3 += __shfl_xor_sync(0xffffffffu, cm3, 1);
            float fm0 = cm0 + s_raw[OFF_COB + 0];
            float fm1 = cm1 + s_raw[OFF_COB + 1];
            float fm2 = cm2 + s_raw[OFF_COB + 2];
            float fm3 = cm3 + s_raw[OFF_COB + 3];

            float x0 = X[0] + dt * X[1] + hd2 * X[2] + g0 * fm0;
            float x1 = X[1] + dt * X[2] + g1 * fm0;
            float x2 = X[2] + g2 * fm0;
            float x3 = X[3] + dt * X[4] + hd2 * X[5] + g0 * fm1;
            float x4 = X[4] + dt * X[5] + g1 * fm1;
            float x5 = X[5] + g2 * fm1;
            X[0] = x0; X[1] = x1; X[2] = x2; X[3] = x3; X[4] = x4; X[5] = x5;
            float Gs[6] = {gt0 * fm2, gt1 * fm2, gt2 * fm2, gt3 * fm3, gt4 * fm3, gt5 * fm3};
#pragma unroll
            for (int ccx = 0; ccx < 6; ccx++) {
                P[0][ccx] += dt * P[1][ccx] + hd2 * P[2][ccx];
                P[1][ccx] += dt * P[2][ccx];
                P[3][ccx] += dt * P[4][ccx] + hd2 * P[5][ccx];
                P[4][ccx] += dt * P[5][ccx];
            }
#pragma unroll
            for (int rr = 0; rr < 6; rr++) {
                P[rr][0] += dt * P[rr][1] + hd2 * P[rr][2];
                P[rr][1] += dt * P[rr][2];
                P[rr][3] += dt * P[rr][4] + hd2 * P[rr][5];
                P[rr][4] += dt * P[rr][5];
            }
#pragma unroll
            for (int i = 0; i < 6; i++)
#pragma unroll
                for (int j = 0; j < 6; j++) P[i][j] += Gs[i] * Gs[j];

            if (valid && half == 0) {
                float sx = sqrtf(P[0][0]);
                float sy = sqrtf(P[3][3]);
                float rho = __fdividef(P[0][3] + P[3][0], 2.0f * sx * sy);
                size_t o = ((size_t)t * B + e) * 5;
                out[o + 0] = X[0];
                out[o + 1] = X[3];
                out[o + 2] = sx;
                out[o + 3] = sy;
                out[o + 4] = rho;
            }
        }
    }
}

extern "C" void kernel_launch(void* const* d_in, const int* in_sizes, int n_in,
                              void* d_out, int out_size) {
    const float* hist  = (const float*)d_in[0];
    const float* psx   = (const float*)d_in[1];
    const float* psy   = (const float*)d_in[2];
    const float* vsx   = (const float*)d_in[3];
    const float* vsy   = (const float*)d_in[4];
    const float* asx   = (const float*)d_in[5];
    const float* asy   = (const float*)d_in[6];
    const float* jerk  = (const float*)d_in[7];
    const float* coefG = (const float*)d_in[8];
    const float* GR    = (const float*)d_in[9];
    const float* cfW   = (const float*)d_in[10];
    const float* cfb   = (const float*)d_in[11];
    const float* Wih   = (const float*)d_in[12];
    const float* Whh   = (const float*)d_in[13];
    const float* bih   = (const float*)d_in[14];
    const float* bhh   = (const float*)d_in[15];
    const float* coW   = (const float*)d_in[16];
    const float* cob   = (const float*)d_in[17];
    float* out = (float*)d_out;

    const int T = 16;
    int B  = in_sizes[0] / (2 * T);
    int LP = out_size / (B * 5);

    size_t smem = (size_t)SMEM_FLOATS * sizeof(float);  // 154688 bytes
    cudaFuncSetAttribute(kalman_lstm_kernel,
                         cudaFuncAttributeMaxDynamicSharedMemorySize, (int)smem);

    int grid = (B + EL - 1) / EL;
    kalman_lstm_kernel<<<grid, TB, smem>>>(
        hist, psx, psy, vsx, vsy, asx, asy, jerk, coefG, GR,
        cfW, cfb, Wih, Whh, bih, bhh, coW, cob, out, B, LP);
}

// round 17
// speedup vs baseline: 2.7870x; 1.1683x over previous
#include <cuda_runtime.h>
#include <cstdint>

#define TB  256
#define EL  128       // elements per CTA
#define SA  68        // act tile row stride (floats)
#define GS  17        // per-warp gbuf col stride

// ---- smem float offsets ----
#define OFF_BIAS 0                      // float4[32]
#define OFF_CF   128                    // float[32*8]
#define OFF_CO   384                    // float4[32]
#define OFF_COB  512                    // float[4] (+pad to 528)
#define OFF_AB   528                    // act big [128][SA]
#define OFF_B4   (OFF_AB + 128*SA)      // packed W: uint4[8 kt][128 n * 4 tq]
#define OFF_G    (OFF_B4 + 16384)       // 8 warps x [32 col][GS]
#define SMEM_FLOATS (OFF_G + 8*32*GS)   // 29968 floats = 119872 B

extern __shared__ float s_raw[];

__device__ __forceinline__ float fsig(float x) { float e = __expf(-x); return __fdividef(1.f, 1.f + e); }
__device__ __forceinline__ float ftanh(float x) { float e = __expf(2.f * x); return 1.f - __fdividef(2.f, e + 1.f); }
__device__ __forceinline__ uint32_t tf32b(float f) {
    uint32_t u; asm("cvt.rna.tf32.f32 %0, %1;" : "=r"(u) : "f"(f)); return u;
}
__device__ __forceinline__ void mma8(float* d, const uint32_t* a, uint32_t b0, uint32_t b1) {
    asm volatile(
        "mma.sync.aligned.m16n8k8.row.col.f32.tf32.tf32.f32 "
        "{%0,%1,%2,%3}, {%4,%5,%6,%7}, {%8,%9}, {%0,%1,%2,%3};"
        : "+f"(d[0]), "+f"(d[1]), "+f"(d[2]), "+f"(d[3])
        : "r"(a[0]), "r"(a[1]), "r"(a[2]), "r"(a[3]), "r"(b0), "r"(b1));
}

__global__ void __launch_bounds__(TB, 1) kalman_lstm_kernel(
    const float* __restrict__ hist,
    const float* __restrict__ p_psx, const float* __restrict__ p_psy,
    const float* __restrict__ p_vsx, const float* __restrict__ p_vsy,
    const float* __restrict__ p_asx, const float* __restrict__ p_asy,
    const float* __restrict__ p_jerk, const float* __restrict__ p_coefG,
    const float* __restrict__ p_GR,
    const float* __restrict__ cfW, const float* __restrict__ cfb,
    const float* __restrict__ Wih, const float* __restrict__ Whh,
    const float* __restrict__ bih, const float* __restrict__ bhh,
    const float* __restrict__ coW, const float* __restrict__ cob,
    float* __restrict__ out,
    int B, int LP)
{
    const int tid = threadIdx.x;
    const int w = tid >> 5;
    const int lane = tid & 31;
    const int gr = lane >> 2, tq = lane & 3;
    const int rb = w * 16;             // my m-tile rows == my elements
    const int erow = lane >> 1;        // element row within tile (0..15)
    const int el = rb + erow;          // my element (CTA-local)
    const int half = lane & 1;         // j-half
    uint32_t* s_u32 = reinterpret_cast<uint32_t*>(s_raw);

    // ---- small tables ----
    if (tid < 32) {
        int j = tid;
        reinterpret_cast<float4*>(s_raw + OFF_BIAS)[j] = make_float4(
            bih[j] + bhh[j],           bih[32 + j] + bhh[32 + j],
            bih[64 + j] + bhh[64 + j], bih[96 + j] + bhh[96 + j]);
        reinterpret_cast<float4*>(s_raw + OFF_CO)[j] = make_float4(
            coW[j], coW[32 + j], coW[64 + j], coW[96 + j]);
#pragma unroll
        for (int k = 0; k < 6; k++) s_raw[OFF_CF + j * 8 + k] = cfW[j * 6 + k];
        s_raw[OFF_CF + j * 8 + 6] = cfb[j];
        s_raw[OFF_CF + j * 8 + 7] = 0.0f;
    }
    if (tid == 32) {
        s_raw[OFF_COB + 0] = cob[0]; s_raw[OFF_COB + 1] = cob[1];
        s_raw[OFF_COB + 2] = cob[2]; s_raw[OFF_COB + 3] = cob[3];
    }

    // ---- packed weight tile: uint4 {bb(k), bb(k+4), bs(k), bs(k+4)} ----
    // row n = 32*chunk + 4*q + gate ; j = 8*chunk + q ; k = kt*8 + tq
    {
        int n = tid & 127;
        int gate = n & 3, q = (n >> 2) & 7, ch = n >> 5;
        int j = ch * 8 + q;
        const float* wi = Wih + (gate * 32 + j) * 32;
        const float* wh = Whh + (gate * 32 + j) * 32;
        int kt0 = (tid >> 7) * 4;
#pragma unroll
        for (int kk = 0; kk < 4; kk++) {
            int kt = kt0 + kk;
#pragma unroll
            for (int t4 = 0; t4 < 4; t4++) {
                int k0 = kt * 8 + t4, k1 = k0 + 4;
                float w0 = (k0 < 32) ? wi[k0] : wh[k0 - 32];
                float w1 = (k1 < 32) ? wi[k1] : wh[k1 - 32];
                uint32_t b0 = tf32b(w0), b1 = tf32b(w1);
                uint32_t s0 = tf32b(w0 - __uint_as_float(b0));
                uint32_t s1 = tf32b(w1 - __uint_as_float(b1));
                reinterpret_cast<uint4*>(s_u32 + OFF_B4)[kt * 512 + n * 4 + t4] =
                    make_uint4(b0, b1, s0, s1);
            }
        }
    }
    // zero act tile
    for (int i = tid; i < 128 * SA; i += TB) s_raw[OFF_AB + i] = 0.0f;
    __syncthreads();   // ONLY CTA barrier

    // ---- per-thread Kalman (duplicated across the 2 halves of an element) ----
    const float dt = 0.2f, hd2 = 0.02f;
    const float g0 = (float)(0.2 * 0.2 * 0.2 / 6.0), g1 = 0.02f, g2 = 0.2f;
    const int e_raw = blockIdx.x * EL + el;
    const bool valid = e_raw < B;
    const int e = valid ? e_raw : (B - 1);
    const float2* hist2 = reinterpret_cast<const float2*>(hist);

    float tg[6];
#pragma unroll
    for (int i = 0; i < 6; i++) tg[i] = tanhf(p_coefG[i]);
    const float jk0 = p_jerk[0], jk1 = p_jerk[1];
    const float Ghx0 = g0 * tg[0] * jk0, Ghx1 = g1 * tg[1] * jk0, Ghx2 = g2 * tg[2] * jk0;
    const float Ghy0 = g0 * tg[3] * jk1, Ghy1 = g1 * tg[4] * jk1, Ghy2 = g2 * tg[5] * jk1;
    const float gt0 = g0 * tg[0], gt1 = g1 * tg[1], gt2 = g2 * tg[2];
    const float gt3 = g0 * tg[3], gt4 = g1 * tg[4], gt5 = g2 * tg[5];
    const float gr0_ = p_GR[0], gr1_ = p_GR[1];
    const float R00 = gr0_ * gr0_, R01 = gr0_ * gr1_, R11 = gr1_ * gr1_;

    float2 z0 = hist2[e];
    float2 z1 = hist2[(size_t)B + e];
    float X[6];
    X[0] = z0.x; X[1] = (z1.x - z0.x) / dt; X[2] = 0.0f;
    X[3] = (z1.y - z0.y) / dt; X[4] = 0.0f; X[5] = 0.0f;
    float P[6][6];
#pragma unroll
    for (int i = 0; i < 6; i++)
#pragma unroll
        for (int j = 0; j < 6; j++) P[i][j] = 0.0f;
    {
        float d0 = p_psx[0], d1 = p_vsx[0], d2 = p_asx[0];
        float d3 = p_psy[0], d4 = p_vsy[0], d5 = p_asy[0];
        P[0][0] = d0 * d0; P[1][1] = d1 * d1; P[2][2] = d2 * d2;
        P[3][3] = d3 * d3; P[4][4] = d4 * d4; P[5][5] = d5 * d5;
    }
    float creg[4][4];
#pragma unroll
    for (int c = 0; c < 4; c++)
#pragma unroll
        for (int q = 0; q < 4; q++) creg[c][q] = 0.0f;

    float* G = s_raw + OFF_G + w * 32 * GS;   // my warp's gate staging
    const uint4* B4 = reinterpret_cast<const uint4*>(s_u32 + OFF_B4);
    const int TS = 15 + LP;

#pragma unroll 1
    for (int step = 0; step < TS; step++) {
        // ---- feat: my element's m rows (m = half*16 .. +15) -> A tile ----
        {
            const float4* cf = reinterpret_cast<const float4*>(s_raw + OFF_CF);
#pragma unroll
            for (int m0 = 0; m0 < 16; m0 += 4) {
                uint4 vb;
                uint32_t* pb = &vb.x;
#pragma unroll
                for (int qq = 0; qq < 4; qq++) {
                    int m = half * 16 + m0 + qq;
                    float4 a = cf[m * 2];
                    float4 b = cf[m * 2 + 1];
                    float acc = b.z;
                    acc = fmaf(a.x, X[0], acc);
                    acc = fmaf(a.y, X[1], acc);
                    acc = fmaf(a.z, X[2], acc);
                    acc = fmaf(a.w, X[3], acc);
                    acc = fmaf(b.x, X[4], acc);
                    acc = fmaf(b.y, X[5], acc);
                    pb[qq] = tf32b(ftanh(acc));
                }
                int k = half * 16 + m0;
                *reinterpret_cast<uint4*>(s_u32 + OFF_AB + el * SA + k) = vb;
            }
        }
        __syncwarp();   // feat (+ prev-step h) visible to my warp's fragment loads

        // ---- A fragments for my m-tile, all k ----
        uint32_t ab[8][4];
#pragma unroll
        for (int kt = 0; kt < 8; kt++) {
            int r = OFF_AB + (rb + gr) * SA + kt * 8 + tq;
            ab[kt][0] = s_u32[r];
            ab[kt][1] = s_u32[r + 8 * SA];
            ab[kt][2] = s_u32[r + 4];
            ab[kt][3] = s_u32[r + 8 * SA + 4];
        }
        __syncwarp();   // all fragment loads done before chunk-0 h writes

        float cm0 = 0.f, cm1 = 0.f, cm2 = 0.f, cm3 = 0.f;

#pragma unroll
        for (int chunk = 0; chunk < 4; chunk++) {
            float d[4][4];
#pragma unroll
            for (int nt = 0; nt < 4; nt++)
#pragma unroll
                for (int k4 = 0; k4 < 4; k4++) d[nt][k4] = 0.0f;

#pragma unroll
            for (int kt = 0; kt < 8; kt++) {
#pragma unroll
                for (int nt = 0; nt < 4; nt++) {
                    uint4 bw = B4[kt * 512 + (chunk * 32 + nt * 8 + gr) * 4 + tq];
                    mma8(d[nt], ab[kt], bw.x, bw.y);   // big x big
                    mma8(d[nt], ab[kt], bw.z, bw.w);   // big x weight-residual
                }
            }

            __syncwarp();   // prior epilogue reads of G done
#pragma unroll
            for (int nt = 0; nt < 4; nt++) {
                int c0 = nt * 8 + 2 * tq, c1 = c0 + 1;
                G[c0 * GS + gr]     = d[nt][0];
                G[c1 * GS + gr]     = d[nt][1];
                G[c0 * GS + gr + 8] = d[nt][2];
                G[c1 * GS + gr + 8] = d[nt][3];
            }
            __syncwarp();   // G complete

            // ---- epilogue: my 4 j's of this chunk; h written immediately ----
            const float4* bias4 = reinterpret_cast<const float4*>(s_raw + OFF_BIAS);
            const float4* co4   = reinterpret_cast<const float4*>(s_raw + OFF_CO);
            uint32_t hb[4];
#pragma unroll
            for (int q = 0; q < 4; q++) {
                int jn = half * 4 + q;         // j within chunk (0..7)
                int j  = chunk * 8 + jn;       // global j
                float gi = G[(4 * jn + 0) * GS + erow];
                float gf = G[(4 * jn + 1) * GS + erow];
                float gg = G[(4 * jn + 2) * GS + erow];
                float go = G[(4 * jn + 3) * GS + erow];
                float4 bq = bias4[j];
                gi += bq.x; gf += bq.y; gg += bq.z; go += bq.w;
                float cold = creg[chunk][q];
                float cj = fmaf(fsig(gf), cold, fsig(gi) * ftanh(gg));
                creg[chunk][q] = cj;
                float h = fsig(go) * ftanh(cj);
                hb[q] = tf32b(h);
                float4 cwt = co4[j];
                cm0 = fmaf(cwt.x, h, cm0);
                cm1 = fmaf(cwt.y, h, cm1);
                cm2 = fmaf(cwt.z, h, cm2);
                cm3 = fmaf(cwt.w, h, cm3);
            }
            {
                int k = 32 + chunk * 8 + half * 4;
                *reinterpret_cast<uint4*>(s_u32 + OFF_AB + el * SA + k) =
                    make_uint4(hb[0], hb[1], hb[2], hb[3]);
            }
        }

        // ================= Kalman (per-thread fp32, duplicated per half) ====
        if (step < 15) {
            int t = step + 1;
            float x0 = X[0] + dt * X[1] + hd2 * X[2];
            float x1 = X[1] + dt * X[2];
            float x3 = X[3] + dt * X[4] + hd2 * X[5];
            float x4 = X[4] + dt * X[5];
            X[0] = x0; X[1] = x1; X[3] = x3; X[4] = x4;
#pragma unroll
            for (int ccx = 0; ccx < 6; ccx++) {
                P[0][ccx] += dt * P[1][ccx] + hd2 * P[2][ccx];
                P[1][ccx] += dt * P[2][ccx];
                P[3][ccx] += dt * P[4][ccx] + hd2 * P[5][ccx];
                P[4][ccx] += dt * P[5][ccx];
            }
#pragma unroll
            for (int rr = 0; rr < 6; rr++) {
                P[rr][0] += dt * P[rr][1] + hd2 * P[rr][2];
                P[rr][1] += dt * P[rr][2];
                P[rr][3] += dt * P[rr][4] + hd2 * P[rr][5];
                P[rr][4] += dt * P[rr][5];
            }
            {
                float gx[3] = {Ghx0, Ghx1, Ghx2}, gy[3] = {Ghy0, Ghy1, Ghy2};
#pragma unroll
                for (int a = 0; a < 3; a++)
#pragma unroll
                    for (int bb = 0; bb < 3; bb++) {
                        P[a][bb]         += gx[a] * gx[bb];
                        P[3 + a][3 + bb] += gy[a] * gy[bb];
                    }
            }
            float2 z = hist2[(size_t)t * B + e];
            float yx = z.x - X[0], yy = z.y - X[3];
            float S00 = P[0][0] + R00, S01 = P[0][3] + R01;
            float S10 = P[3][0] + R01, S11 = P[3][3] + R11;
            float rdet = 1.0f / (S00 * S11 - S01 * S10);
            float si00 =  S11 * rdet, si01 = -S01 * rdet;
            float si10 = -S10 * rdet, si11 =  S00 * rdet;
            float K0[6], K1[6];
#pragma unroll
            for (int i = 0; i < 6; i++) {
                K0[i] = P[i][0] * si00 + P[i][3] * si10;
                K1[i] = P[i][0] * si01 + P[i][3] * si11;
            }
#pragma unroll
            for (int i = 0; i < 6; i++) X[i] += K0[i] * yx + K1[i] * yy;
            float r0[6], r3[6];
#pragma unroll
            for (int j = 0; j < 6; j++) { r0[j] = P[0][j]; r3[j] = P[3][j]; }
#pragma unroll
            for (int i = 0; i < 6; i++)
#pragma unroll
                for (int j = 0; j < 6; j++) P[i][j] -= K0[i] * r0[j] + K1[i] * r3[j];
        } else {
            int t = step - 15;
            // combine command partials across the 2 j-halves (lanes 2k / 2k+1)
            cm0 += __shfl_xor_sync(0xffffffffu, cm0, 1);
            cm1 += __shfl_xor_sync(0xffffffffu, cm1, 1);
            cm2 += __shfl_xor_sync(0xffffffffu, cm2, 1);
            cm3 += __shfl_xor_sync(0xffffffffu, cm3, 1);
            float fm0 = cm0 + s_raw[OFF_COB + 0];
            float fm1 = cm1 + s_raw[OFF_COB + 1];
            float fm2 = cm2 + s_raw[OFF_COB + 2];
            float fm3 = cm3 + s_raw[OFF_COB + 3];

            float x0 = X[0] + dt * X[1] + hd2 * X[2] + g0 * fm0;
            float x1 = X[1] + dt * X[2] + g1 * fm0;
            float x2 = X[2] + g2 * fm0;
            float x3 = X[3] + dt * X[4] + hd2 * X[5] + g0 * fm1;
            float x4 = X[4] + dt * X[5] + g1 * fm1;
            float x5 = X[5] + g2 * fm1;
            X[0] = x0; X[1] = x1; X[2] = x2; X[3] = x3; X[4] = x4; X[5] = x5;
            float Gs[6] = {gt0 * fm2, gt1 * fm2, gt2 * fm2, gt3 * fm3, gt4 * fm3, gt5 * fm3};
#pragma unroll
            for (int ccx = 0; ccx < 6; ccx++) {
                P[0][ccx] += dt * P[1][ccx] + hd2 * P[2][ccx];
                P[1][ccx] += dt * P[2][ccx];
                P[3][ccx] += dt * P[4][ccx] + hd2 * P[5][ccx];
                P[4][ccx] += dt * P[5][ccx];
            }
#pragma unroll
            for (int rr = 0; rr < 6; rr++) {
                P[rr][0] += dt * P[rr][1] + hd2 * P[rr][2];
                P[rr][1] += dt * P[rr][2];
                P[rr][3] += dt * P[rr][4] + hd2 * P[rr][5];
                P[rr][4] += dt * P[rr][5];
            }
#pragma unroll
            for (int i = 0; i < 6; i++)
#pragma unroll
                for (int j = 0; j < 6; j++) P[i][j] += Gs[i] * Gs[j];

            if (valid && half == 0) {
                float sx = sqrtf(P[0][0]);
                float sy = sqrtf(P[3][3]);
                float rho = __fdividef(P[0][3] + P[3][0], 2.0f * sx * sy);
                size_t o = ((size_t)t * B + e) * 5;
                out[o + 0] = X[0];
                out[o + 1] = X[3];
                out[o + 2] = sx;
                out[o + 3] = sy;
                out[o + 4] = rho;
            }
        }
    }
}

extern "C" void kernel_launch(void* const* d_in, const int* in_sizes, int n_in,
                              void* d_out, int out_size) {
    const float* hist  = (const float*)d_in[0];
    const float* psx   = (const float*)d_in[1];
    const float* psy   = (const float*)d_in[2];
    const float* vsx   = (const float*)d_in[3];
    const float* vsy   = (const float*)d_in[4];
    const float* asx   = (const float*)d_in[5];
    const float* asy   = (const float*)d_in[6];
    const float* jerk  = (const float*)d_in[7];
    const float* coefG = (const float*)d_in[8];
    const float* GR    = (const float*)d_in[9];
    const float* cfW   = (const float*)d_in[10];
    const float* cfb   = (const float*)d_in[11];
    const float* Wih   = (const float*)d_in[12];
    const float* Whh   = (const float*)d_in[13];
    const float* bih   = (const float*)d_in[14];
    const float* bhh   = (const float*)d_in[15];
    const float* coW   = (const float*)d_in[16];
    const float* cob   = (const float*)d_in[17];
    float* out = (float*)d_out;

    const int T = 16;
    int B  = in_sizes[0] / (2 * T);
    int LP = out_size / (B * 5);

    size_t smem = (size_t)SMEM_FLOATS * sizeof(float);  // 119872 bytes
    cudaFuncSetAttribute(kalman_lstm_kernel,
                         cudaFuncAttributeMaxDynamicSharedMemorySize, (int)smem);

    int grid = (B + EL - 1) / EL;
    kalman_lstm_kernel<<<grid, TB, smem>>>(
        hist, psx, psy, vsx, vsy, asx, asy, jerk, coefG, GR,
        cfW, cfb, Wih, Whh, bih, bhh, coW, cob, out, B, LP);
}